// round 1
// baseline (speedup 1.0000x reference)
#include <cuda_runtime.h>
#include <cstdint>
#include <math.h>

#define NB 8
#define NC 80
#define NPTS 25200
#define KTOP 256
#define MAXB 100
#define NMS_T 0.6f
#define TOPK_CAP 1024
#define NHIST 16384

// ---------------- scratch (static device globals; no allocation) ----------------
__device__ float4 g_boxes4[NB * NPTS];                         // [B][N] yxyx
__device__ float  g_scoresT[(size_t)NB * NC * NPTS];           // [B][C][N]
__device__ float  g_cand_val[NB * NC * KTOP];                  // [B][C][K]
__device__ float4 g_cand_boxes4[NB * NC * KTOP];               // [B][C][K]
__device__ float  g_kept[NB * NC * KTOP];                      // [B][C][K]

// anchors / 640, grouped by level
__constant__ float c_anch[3][3][2] = {
    {{12.0f/640.0f, 16.0f/640.0f}, {19.0f/640.0f, 36.0f/640.0f}, {40.0f/640.0f, 28.0f/640.0f}},
    {{36.0f/640.0f, 75.0f/640.0f}, {76.0f/640.0f, 55.0f/640.0f}, {72.0f/640.0f, 146.0f/640.0f}},
    {{142.0f/640.0f,110.0f/640.0f},{192.0f/640.0f,243.0f/640.0f},{459.0f/640.0f,401.0f/640.0f}}};

__device__ __forceinline__ float sigm(float x) { return 1.0f / (1.0f + expf(-x)); }

// ---------------- Stage 1: decode ----------------
// Tiles of 80 consecutive anchor points. Input for anchors [n0,n0+80) is the
// contiguous float range [n0*85, n0*85+6800) of that level slab.
// Tiles per image: lvl0 240, lvl1 60, lvl2 15 -> 315. Grid = 8*315 = 2520.
__global__ __launch_bounds__(256) void decode_kernel(
    const float* __restrict__ x3, const float* __restrict__ x4, const float* __restrict__ x5)
{
    __shared__ float sIn[80 * 85];
    __shared__ float sObj[80];

    int blk = blockIdx.x;
    int b = blk / 315;
    int t = blk % 315;
    const float* src; int W, lvlOff, tloc, lvl;
    if (t < 240)      { lvl = 0; W = 80; lvlOff = 0;     tloc = t;       src = x3; }
    else if (t < 300) { lvl = 1; W = 40; lvlOff = 19200; tloc = t - 240; src = x4; }
    else              { lvl = 2; W = 20; lvlOff = 24000; tloc = t - 300; src = x5; }

    int nLocBase = tloc * 80;
    const float* base = src + (size_t)b * W * W * 255 + (size_t)nLocBase * 85;
    int tid = threadIdx.x;

    for (int i = tid; i < 80 * 85; i += 256) sIn[i] = base[i];
    __syncthreads();

    int nGlobBase = lvlOff + nLocBase;
    float invW = 1.0f / (float)W;

    if (tid < 80) {
        const float* d = &sIn[tid * 85];
        int nLoc = nLocBase + tid;
        int a = nLoc % 3;
        int cell = nLoc / 3;
        int wq = cell % W;
        int hq = cell / W;
        float sx = sigm(d[0]);
        float sy = sigm(d[1]);
        float xc = (sx + (float)wq) * invW;
        float yc = (sy + (float)hq) * invW;
        float bw = expf(d[2]) * c_anch[lvl][a][0];
        float bh = expf(d[3]) * c_anch[lvl][a][1];
        float4 bx;
        bx.x = yc - bh * 0.5f;
        bx.y = xc - bw * 0.5f;
        bx.z = yc + bh * 0.5f;
        bx.w = xc + bw * 0.5f;
        g_boxes4[(size_t)b * NPTS + nGlobBase + tid] = bx;
        sObj[tid] = sigm(d[4]);
    }
    __syncthreads();

    // scores: 80 classes x 80 anchors; consecutive threads -> consecutive n (coalesced)
    for (int p = tid; p < 6400; p += 256) {
        int al = p % 80;
        int c  = p / 80;
        float v = sigm(sIn[al * 85 + 5 + c]) * sObj[al];
        g_scoresT[((size_t)b * NC + c) * NPTS + nGlobBase + al] = v;
    }
}

// ---------------- Stage 2: per-class top-256 (sorted) ----------------
// One CTA per (b,c). Histogram-select + bitonic sort of packed 64-bit keys.
extern __shared__ char smem_dyn[];
#define TOPK_SMEM (8 * TOPK_CAP + 4 * NPTS + 4 * NHIST + 16)

__global__ __launch_bounds__(256) void topk_kernel()
{
    unsigned long long* keys = (unsigned long long*)smem_dyn;                      // 8192 B
    float*    srow  = (float*)(smem_dyn + 8 * TOPK_CAP);                           // 100800 B
    unsigned* hist  = (unsigned*)(smem_dyn + 8 * TOPK_CAP + 4 * NPTS);             // 65536 B
    int*      sInts = (int*)(smem_dyn + 8 * TOPK_CAP + 4 * NPTS + 4 * NHIST);      // [0]=cnt [1]=thr
    __shared__ int chunkSum[256];

    int bc = blockIdx.x;
    int tid = threadIdx.x;
    const float* row = g_scoresT + (size_t)bc * NPTS;

    for (int i = tid; i < NHIST; i += 256) hist[i] = 0;
    if (tid == 0) sInts[0] = 0;
    __syncthreads();

    for (int i = tid; i < NPTS; i += 256) {
        float v = row[i];
        srow[i] = v;
        atomicAdd(&hist[__float_as_uint(v) >> 16], 1u);
    }
    __syncthreads();

    { // per-thread chunk sums (64 buckets each)
        unsigned s = 0;
        int base = tid * 64;
        #pragma unroll 8
        for (int k = 0; k < 64; k++) s += hist[base + k];
        chunkSum[tid] = (int)s;
    }
    __syncthreads();

    if (tid == 0) {
        int cum = 0, thr = 0;
        for (int c = 255; c >= 0; --c) {
            if (cum + chunkSum[c] >= KTOP) {
                for (int bkt = c * 64 + 63; ; --bkt) {
                    cum += (int)hist[bkt];
                    if (cum >= KTOP) { thr = bkt; break; }
                }
                break;
            }
            cum += chunkSum[c];
        }
        sInts[1] = thr;
    }
    __syncthreads();

    unsigned thr = (unsigned)sInts[1];
    for (int i = tid; i < NPTS; i += 256) {
        unsigned bits = __float_as_uint(srow[i]);
        if ((bits >> 16) >= thr) {
            int pos = atomicAdd(&sInts[0], 1);
            if (pos < TOPK_CAP)
                keys[pos] = ((unsigned long long)bits << 32) | (unsigned)(~(unsigned)i);
        }
    }
    __syncthreads();
    int cnt = sInts[0]; if (cnt > TOPK_CAP) cnt = TOPK_CAP;
    for (int i = tid; i < TOPK_CAP; i += 256) if (i >= cnt) keys[i] = 0ULL;
    __syncthreads();

    // bitonic sort, descending (val desc, idx asc via ~idx in low bits)
    for (unsigned k = 2; k <= TOPK_CAP; k <<= 1) {
        for (unsigned j = k >> 1; j > 0; j >>= 1) {
            for (unsigned i = tid; i < TOPK_CAP; i += 256) {
                unsigned l = i ^ j;
                if (l > i) {
                    unsigned long long a = keys[i], bb = keys[l];
                    bool up = ((i & k) == 0);
                    if (up ? (a < bb) : (a > bb)) { keys[i] = bb; keys[l] = a; }
                }
            }
            __syncthreads();
        }
    }

    // emit top-256 (cnt >= 256 guaranteed: >=K elems in buckets >= thr)
    unsigned long long key = keys[tid];
    float val = __uint_as_float((unsigned)(key >> 32));
    unsigned idx = ~(unsigned)key;
    int b = bc / NC;
    g_cand_val[(size_t)bc * KTOP + tid] = val;
    g_cand_boxes4[(size_t)bc * KTOP + tid] = g_boxes4[(size_t)b * NPTS + idx];
}

// ---------------- Stage 3: bitmask greedy NMS ----------------
__global__ __launch_bounds__(256) void nms_kernel()
{
    __shared__ float sy0[256], sx0[256], sy1[256], sx1[256], sar[256];
    __shared__ unsigned smask[256][8];
    __shared__ unsigned skeep[8];

    int bc = blockIdx.x;
    int tid = threadIdx.x;
    float4 bb = g_cand_boxes4[(size_t)bc * KTOP + tid];
    sy0[tid] = bb.x; sx0[tid] = bb.y; sy1[tid] = bb.z; sx1[tid] = bb.w;
    float ar = (bb.z - bb.x) * (bb.w - bb.y);
    sar[tid] = ar;
    __syncthreads();

    unsigned m[8];
    #pragma unroll
    for (int w = 0; w < 8; w++) m[w] = 0;

    float y0 = bb.x, x0 = bb.y, y1 = bb.z, x1 = bb.w;
    for (int j = 0; j < 256; ++j) {   // uniform j -> broadcast smem reads
        if (j > tid) {
            float iy = fmaxf(fminf(y1, sy1[j]) - fmaxf(y0, sy0[j]), 0.0f);
            float ix = fmaxf(fminf(x1, sx1[j]) - fmaxf(x0, sx0[j]), 0.0f);
            float inter = iy * ix;
            float uni = ar + sar[j] - inter;
            if (inter > NMS_T * fmaxf(uni, 1e-9f)) m[j >> 5] |= (1u << (j & 31));
        }
    }
    #pragma unroll
    for (int w = 0; w < 8; w++) smask[tid][w] = m[w];
    __syncthreads();

    if (tid == 0) {
        unsigned kp[8];
        #pragma unroll
        for (int w = 0; w < 8; w++) kp[w] = 0xFFFFFFFFu;
        for (int i = 0; i < 256; ++i) {
            if ((kp[i >> 5] >> (i & 31)) & 1u) {
                #pragma unroll
                for (int w = 0; w < 8; w++) kp[w] &= ~smask[i][w];
            }
        }
        #pragma unroll
        for (int w = 0; w < 8; w++) skeep[w] = kp[w];
    }
    __syncthreads();

    float val = g_cand_val[(size_t)bc * KTOP + tid];
    bool keep = (skeep[tid >> 5] >> (tid & 31)) & 1u;
    g_kept[(size_t)bc * KTOP + tid] = keep ? val : 0.0f;
}

// ---------------- Stage 4: 80-way merge top-100 + outputs ----------------
#define FINAL_SMEM (4 * NC * KTOP + 8 * MAXB)

__global__ __launch_bounds__(256) void final_kernel(float* __restrict__ out)
{
    extern __shared__ char fsm[];
    float* kept = (float*)fsm;                                       // 20480 floats
    unsigned long long* winners = (unsigned long long*)(fsm + 4 * NC * KTOP); // 100 keys
    __shared__ int sCount;

    int b = blockIdx.x;
    int tid = threadIdx.x;
    for (int i = tid; i < NC * KTOP; i += 256) kept[i] = g_kept[(size_t)b * NC * KTOP + i];
    if (tid == 0) sCount = 0;
    __syncthreads();

    if (tid < 32) {
        int lane = tid;
        unsigned long long key[3];
        #pragma unroll
        for (int s = 0; s < 3; s++) {
            int c = lane + s * 32;
            if (c < NC) {
                float v = kept[c * KTOP];  // head is never suppressed, always > 0
                key[s] = ((unsigned long long)__float_as_uint(v) << 32) |
                         (unsigned)(~(unsigned)(c * KTOP));
            } else key[s] = 0ULL;
        }
        for (int m = 0; m < MAXB; m++) {
            unsigned long long best = key[0];
            if (key[1] > best) best = key[1];
            if (key[2] > best) best = key[2];
            #pragma unroll
            for (int off = 16; off; off >>= 1) {
                unsigned long long o = __shfl_xor_sync(0xffffffffu, best, off);
                if (o > best) best = o;
            }
            if (lane == 0) winners[m] = best;
            if (best != 0ULL) {
                unsigned flat = ~(unsigned)best;
                int c = (int)(flat >> 8);
                if ((c & 31) == lane) {        // owner advances its cursor
                    int s = c >> 5;
                    int k2 = (int)(flat & 255) + 1;
                    int base2 = c * KTOP;
                    while (k2 < KTOP && kept[base2 + k2] == 0.0f) k2++;
                    key[s] = (k2 < KTOP)
                        ? (((unsigned long long)__float_as_uint(kept[base2 + k2]) << 32) |
                           (unsigned)(~(unsigned)(base2 + k2)))
                        : 0ULL;
                }
            }
        }
    }
    __syncthreads();

    if (tid < MAXB) {
        unsigned long long wk = winners[tid];
        float val = __uint_as_float((unsigned)(wk >> 32));
        bool valid = (wk != 0ULL) && (val > 0.0f);
        float4 bx = make_float4(0.f, 0.f, 0.f, 0.f);
        float cls = 0.0f, sc = 0.0f;
        if (valid) {
            unsigned flat = ~(unsigned)wk;
            int c = (int)(flat >> 8);
            int k2 = (int)(flat & 255);
            float4 bb = g_cand_boxes4[((size_t)b * NC + c) * KTOP + k2];
            bx.x = fminf(fmaxf(bb.x, 0.0f), 1.0f);
            bx.y = fminf(fmaxf(bb.y, 0.0f), 1.0f);
            bx.z = fminf(fmaxf(bb.z, 0.0f), 1.0f);
            bx.w = fminf(fmaxf(bb.w, 0.0f), 1.0f);
            cls = (float)c;
            sc = val;
            atomicAdd(&sCount, 1);
        }
        ((float4*)out)[b * MAXB + tid] = bx;                 // nb
        out[NB * 400 + b * MAXB + tid] = cls;                // nc
        out[NB * 500 + b * MAXB + tid] = sc;                 // ns
    }
    __syncthreads();
    if (tid == 0) out[NB * 600 + b] = (float)sCount;         // num_detections
}

// ---------------- launch ----------------
extern "C" void kernel_launch(void* const* d_in, const int* in_sizes, int n_in,
                              void* d_out, int out_size)
{
    const float* x3 = (const float*)d_in[0];
    const float* x4 = (const float*)d_in[1];
    const float* x5 = (const float*)d_in[2];
    float* out = (float*)d_out;

    cudaFuncSetAttribute(topk_kernel, cudaFuncAttributeMaxDynamicSharedMemorySize, TOPK_SMEM);
    cudaFuncSetAttribute(final_kernel, cudaFuncAttributeMaxDynamicSharedMemorySize, FINAL_SMEM);

    decode_kernel<<<NB * 315, 256>>>(x3, x4, x5);
    topk_kernel<<<NB * NC, 256, TOPK_SMEM>>>();
    nms_kernel<<<NB * NC, 256>>>();
    final_kernel<<<NB, 256, FINAL_SMEM>>>(out);
}

// round 2
// speedup vs baseline: 1.1331x; 1.1331x over previous
#include <cuda_runtime.h>
#include <cstdint>
#include <math.h>

#define NB 8
#define NC 80
#define NPTS 25200
#define KTOP 256
#define MAXB 100
#define NMS_T 0.6f
#define CAP 2048
#define NHIST 8192
#define FHIST 4096
#define FCAP 2048

// ---------------- scratch (static device globals) ----------------
__device__ float4 g_boxes4[NB * NPTS];                       // [B][N] yxyx
__device__ unsigned short g_key16[(size_t)NB * NC * NPTS];   // [B][C][N] approx key (smaller=better)
__device__ float4 g_cand_boxes4[NB * NC * KTOP];             // [B][C][K]
__device__ float  g_kept[NB * NC * KTOP];                    // [B][C][K]

__constant__ float c_anch[3][3][2] = {
    {{12.0f/640.0f, 16.0f/640.0f}, {19.0f/640.0f, 36.0f/640.0f}, {40.0f/640.0f, 28.0f/640.0f}},
    {{36.0f/640.0f, 75.0f/640.0f}, {76.0f/640.0f, 55.0f/640.0f}, {72.0f/640.0f, 146.0f/640.0f}},
    {{142.0f/640.0f,110.0f/640.0f},{192.0f/640.0f,243.0f/640.0f},{459.0f/640.0f,401.0f/640.0f}}};

__device__ __forceinline__ float sigm(float x) { return 1.0f / (1.0f + expf(-x)); }

// Schraudolph approx of e^{-x}: one-sided OVERestimate (<= +6.07% rel), monotone.
// FMA + F2I only (no MUFU).
__device__ __forceinline__ float schr_em(float x) {
    float y = fmaf(x, -12102203.0f, 1065353216.0f);   // 2^23*(127 - x*log2(e))
    return __int_as_float((int)y);
}

// ---------------- Stage 1: decode (boxes exact; keys approx, FMA-only) ----------------
// Tiles of 80 anchors; lvl0 240 tiles, lvl1 60, lvl2 15 -> 315/img. Grid 8*315.
__global__ __launch_bounds__(256) void decode_kernel(
    const float* __restrict__ x3, const float* __restrict__ x4, const float* __restrict__ x5)
{
    __shared__ float sIn[6800];
    __shared__ float sEo1[80];      // 1 + ~e^{-obj}

    int blk = blockIdx.x;
    int b = blk / 315;
    int t = blk - b * 315;
    const float* src; int W, lvlOff, tloc, lvl;
    if (t < 240)      { lvl = 0; W = 80; lvlOff = 0;     tloc = t;       src = x3; }
    else if (t < 300) { lvl = 1; W = 40; lvlOff = 19200; tloc = t - 240; src = x4; }
    else              { lvl = 2; W = 20; lvlOff = 24000; tloc = t - 300; src = x5; }

    int tid = threadIdx.x;
    const float4* base4 = (const float4*)(src + (size_t)b * W * W * 255 + (size_t)tloc * 6800);
    for (int i = tid; i < 1700; i += 256) ((float4*)sIn)[i] = base4[i];
    __syncthreads();

    int nGlobBase = lvlOff + tloc * 80;
    float invW = 1.0f / (float)W;

    if (tid < 80) {
        const float* d = &sIn[tid * 85];
        int nLoc = tloc * 80 + tid;
        int a = nLoc % 3;
        int cell = nLoc / 3;
        int wq = cell % W;
        int hq = cell / W;
        float xc = (sigm(d[0]) + (float)wq) * invW;
        float yc = (sigm(d[1]) + (float)hq) * invW;
        float bw = expf(d[2]) * c_anch[lvl][a][0];
        float bh = expf(d[3]) * c_anch[lvl][a][1];
        float4 bx;
        bx.x = yc - bh * 0.5f;
        bx.y = xc - bw * 0.5f;
        bx.z = yc + bh * 0.5f;
        bx.w = xc + bw * 0.5f;
        g_boxes4[(size_t)b * NPTS + nGlobBase + tid] = bx;
        sEo1[tid] = 1.0f + schr_em(d[4]);
    }
    __syncthreads();

    // keys: 160 threads; q = anchor-quad (fixed per thread), cg = class group of 8
    if (tid < 160) {
        int q = tid % 20, cg = tid / 20;
        int a0 = q * 4;
        float e0 = sEo1[a0], e1 = sEo1[a0+1], e2 = sEo1[a0+2], e3 = sEo1[a0+3];
        const float* p = &sIn[a0 * 85 + 5 + cg];
        unsigned short* gp = g_key16 + ((size_t)b * NC + cg) * NPTS + nGlobBase + a0;
        #pragma unroll 2
        for (int j = 0; j < 10; j++) {
            // key = (1+e^-c)(1+e^-o) = eo1 + e^-c * eo1 ; >= true value
            float d0 = fmaf(schr_em(p[0]),   e0, e0);
            float d1 = fmaf(schr_em(p[85]),  e1, e1);
            float d2 = fmaf(schr_em(p[170]), e2, e2);
            float d3 = fmaf(schr_em(p[255]), e3, e3);
            unsigned lo = __byte_perm(__float_as_uint(d0), __float_as_uint(d1), 0x7632);
            unsigned hi = __byte_perm(__float_as_uint(d2), __float_as_uint(d3), 0x7632);
            *reinterpret_cast<uint2*>(gp) = make_uint2(lo, hi);
            p += 8;
            gp += (size_t)8 * NPTS;
        }
    }
}

// ---------------- Stage 2: fused top-256 select + exact rescore + sort + NMS ----------------
#define OFF_HIST 0
#define OFF_KEYS 32768
#define OFF_CAND 49152
#define OFF_BY0  57344
#define OFF_BX0  58368
#define OFF_BY1  59392
#define OFF_BX1  60416
#define OFF_BAR  61440
#define OFF_MASK 62464
#define OFF_CHNK 70656
#define OFF_INTS 71680
#define TK_SMEM  71744

__global__ __launch_bounds__(256) void topk_nms_kernel(
    const float* __restrict__ x3, const float* __restrict__ x4, const float* __restrict__ x5)
{
    extern __shared__ char sm[];
    unsigned* hist = (unsigned*)(sm + OFF_HIST);
    unsigned long long* keys = (unsigned long long*)(sm + OFF_KEYS);
    int* cand  = (int*)(sm + OFF_CAND);
    float* sy0 = (float*)(sm + OFF_BY0);
    float* sx0 = (float*)(sm + OFF_BX0);
    float* sy1 = (float*)(sm + OFF_BY1);
    float* sx1 = (float*)(sm + OFF_BX1);
    float* sar = (float*)(sm + OFF_BAR);
    unsigned* smask = (unsigned*)(sm + OFF_MASK);   // [256][8]
    int* chunk = (int*)(sm + OFF_CHNK);
    int* sInts = (int*)(sm + OFF_INTS);             // 0:cnt 1:t0 2:S

    int bc = blockIdx.x;
    int b = bc / NC, c = bc - b * NC;
    int tid = threadIdx.x;

    for (int i = tid; i < NHIST; i += 256) hist[i] = 0;
    if (tid == 0) sInts[0] = 0;
    __syncthreads();

    const uint4* r4 = (const uint4*)(g_key16 + (size_t)bc * NPTS);
    for (int i = tid; i < NPTS / 8; i += 256) {
        uint4 v = r4[i];
        atomicAdd(&hist[(v.x & 0xffffu) >> 3], 1u);
        atomicAdd(&hist[v.x >> 19], 1u);
        atomicAdd(&hist[(v.y & 0xffffu) >> 3], 1u);
        atomicAdd(&hist[v.y >> 19], 1u);
        atomicAdd(&hist[(v.z & 0xffffu) >> 3], 1u);
        atomicAdd(&hist[v.z >> 19], 1u);
        atomicAdd(&hist[(v.w & 0xffffu) >> 3], 1u);
        atomicAdd(&hist[v.w >> 19], 1u);
    }
    __syncthreads();
    {
        int s = 0, base = tid * 32;
        #pragma unroll 8
        for (int k = 0; k < 32; k++) s += (int)hist[base + k];
        chunk[tid] = s;
    }
    __syncthreads();
    if (tid == 0) {
        int cum = 0, t0 = NHIST - 1;
        for (int cc = 0; cc < 256; cc++) {
            if (cum + chunk[cc] >= KTOP) {
                int bk = cc * 32;
                for (;; bk++) { cum += (int)hist[bk]; if (cum >= KTOP) break; }
                t0 = bk;
                break;
            }
            cum += chunk[cc];
        }
        sInts[1] = t0;
    }
    __syncthreads();
    int t0 = sInts[1];
    unsigned T16;
    {
        float T0f = __int_as_float((t0 + 1) << 19);     // bucket upper edge
        T16 = __float_as_uint(T0f * 1.16f) >> 16;       // margin covers 1.0607^2 * trunc slack
    }
    for (int i = tid; i < NPTS / 8; i += 256) {
        uint4 v = r4[i]; int n0 = i * 8; unsigned k; int p;
        k = v.x & 0xffffu; if (k <= T16) { p = atomicAdd(&sInts[0], 1); if (p < CAP) cand[p] = n0; }
        k = v.x >> 16;     if (k <= T16) { p = atomicAdd(&sInts[0], 1); if (p < CAP) cand[p] = n0 + 1; }
        k = v.y & 0xffffu; if (k <= T16) { p = atomicAdd(&sInts[0], 1); if (p < CAP) cand[p] = n0 + 2; }
        k = v.y >> 16;     if (k <= T16) { p = atomicAdd(&sInts[0], 1); if (p < CAP) cand[p] = n0 + 3; }
        k = v.z & 0xffffu; if (k <= T16) { p = atomicAdd(&sInts[0], 1); if (p < CAP) cand[p] = n0 + 4; }
        k = v.z >> 16;     if (k <= T16) { p = atomicAdd(&sInts[0], 1); if (p < CAP) cand[p] = n0 + 5; }
        k = v.w & 0xffffu; if (k <= T16) { p = atomicAdd(&sInts[0], 1); if (p < CAP) cand[p] = n0 + 6; }
        k = v.w >> 16;     if (k <= T16) { p = atomicAdd(&sInts[0], 1); if (p < CAP) cand[p] = n0 + 7; }
    }
    __syncthreads();
    int cnt = sInts[0];
    if (cnt > CAP) {        // uniform branch: fallback strict pass (buckets <= t0 only)
        if (tid == 0) sInts[0] = 0;
        __syncthreads();
        unsigned Tb = (((unsigned)(t0 + 1)) << 3) - 1u;
        for (int i = tid; i < NPTS / 8; i += 256) {
            uint4 v = r4[i]; int n0 = i * 8; unsigned k; int p;
            k = v.x & 0xffffu; if (k <= Tb) { p = atomicAdd(&sInts[0], 1); if (p < CAP) cand[p] = n0; }
            k = v.x >> 16;     if (k <= Tb) { p = atomicAdd(&sInts[0], 1); if (p < CAP) cand[p] = n0 + 1; }
            k = v.y & 0xffffu; if (k <= Tb) { p = atomicAdd(&sInts[0], 1); if (p < CAP) cand[p] = n0 + 2; }
            k = v.y >> 16;     if (k <= Tb) { p = atomicAdd(&sInts[0], 1); if (p < CAP) cand[p] = n0 + 3; }
            k = v.z & 0xffffu; if (k <= Tb) { p = atomicAdd(&sInts[0], 1); if (p < CAP) cand[p] = n0 + 4; }
            k = v.z >> 16;     if (k <= Tb) { p = atomicAdd(&sInts[0], 1); if (p < CAP) cand[p] = n0 + 5; }
            k = v.w & 0xffffu; if (k <= Tb) { p = atomicAdd(&sInts[0], 1); if (p < CAP) cand[p] = n0 + 6; }
            k = v.w >> 16;     if (k <= Tb) { p = atomicAdd(&sInts[0], 1); if (p < CAP) cand[p] = n0 + 7; }
        }
        __syncthreads();
        cnt = sInts[0];
        if (cnt > CAP) cnt = CAP;
    }

    // exact rescore of candidates (reads raw logits; tiny MUFU count)
    for (int i = tid; i < cnt; i += 256) {
        int n = cand[i];
        const float* s;
        if (n < 19200)      s = x3 + (size_t)b * 1632000 + (size_t)n * 85;
        else if (n < 24000) s = x4 + (size_t)b * 408000  + (size_t)(n - 19200) * 85;
        else                s = x5 + (size_t)b * 102000  + (size_t)(n - 24000) * 85;
        float sc = sigm(s[5 + c]) * sigm(s[4]);
        keys[i] = ((unsigned long long)__float_as_uint(sc) << 32) | (unsigned)(~(unsigned)n);
    }
    if (tid == 0) {
        int S = 256; while (S < cnt) S <<= 1;
        sInts[2] = S;
    }
    __syncthreads();
    int S = sInts[2];
    for (int i = cnt + tid; i < S; i += 256) keys[i] = 0ULL;
    __syncthreads();

    // bitonic sort descending: (score desc, index asc via ~n)
    for (unsigned k = 2; k <= (unsigned)S; k <<= 1) {
        for (unsigned j = k >> 1; j > 0; j >>= 1) {
            for (unsigned i = tid; i < (unsigned)S; i += 256) {
                unsigned l = i ^ j;
                if (l > i) {
                    unsigned long long a = keys[i], bb = keys[l];
                    bool up = ((i & k) == 0);
                    if (up ? (a < bb) : (a > bb)) { keys[i] = bb; keys[l] = a; }
                }
            }
            __syncthreads();
        }
    }

    // NMS on the exact sorted top-256
    unsigned long long key = keys[tid];
    float val = __uint_as_float((unsigned)(key >> 32));
    unsigned n = ~(unsigned)key;
    float4 bb4 = g_boxes4[(size_t)b * NPTS + n];
    g_cand_boxes4[(size_t)bc * KTOP + tid] = bb4;
    sy0[tid] = bb4.x; sx0[tid] = bb4.y; sy1[tid] = bb4.z; sx1[tid] = bb4.w;
    float ar = (bb4.z - bb4.x) * (bb4.w - bb4.y);
    sar[tid] = ar;
    __syncthreads();

    unsigned m[8];
    #pragma unroll
    for (int w = 0; w < 8; w++) m[w] = 0;
    float y0 = bb4.x, x0 = bb4.y, y1 = bb4.z, x1 = bb4.w;
    for (int j = 0; j < KTOP; ++j) {
        if (j > tid) {
            float iy = fmaxf(fminf(y1, sy1[j]) - fmaxf(y0, sy0[j]), 0.0f);
            float ix = fmaxf(fminf(x1, sx1[j]) - fmaxf(x0, sx0[j]), 0.0f);
            float inter = iy * ix;
            float uni = ar + sar[j] - inter;
            if (inter > NMS_T * fmaxf(uni, 1e-9f)) m[j >> 5] |= (1u << (j & 31));
        }
    }
    #pragma unroll
    for (int w = 0; w < 8; w++) smask[tid * 8 + w] = m[w];
    __syncthreads();

    if (tid == 0) {
        unsigned kp[8];
        #pragma unroll
        for (int w = 0; w < 8; w++) kp[w] = 0xFFFFFFFFu;
        for (int i = 0; i < KTOP; ++i) {
            if ((kp[i >> 5] >> (i & 31)) & 1u) {
                #pragma unroll
                for (int w = 0; w < 8; w++) kp[w] &= ~smask[i * 8 + w];
            }
        }
        #pragma unroll
        for (int w = 0; w < 8; w++) chunk[w] = (int)kp[w];
    }
    __syncthreads();

    bool keep = ((unsigned)chunk[tid >> 5] >> (tid & 31)) & 1u;
    g_kept[(size_t)bc * KTOP + tid] = keep ? val : 0.0f;
}

// ---------------- Stage 4: per-image top-100 via histogram + sort ----------------
__global__ __launch_bounds__(256) void final_kernel(float* __restrict__ out)
{
    __shared__ unsigned fhist[FHIST];
    __shared__ unsigned long long fkeys[FCAP];
    __shared__ int fchunk[256];
    __shared__ int ints[4];   // 0:cnt 1:t0 2:S 3:numdet

    int b = blockIdx.x, tid = threadIdx.x;
    const float* row = g_kept + (size_t)b * NC * KTOP;

    for (int i = tid; i < FHIST; i += 256) fhist[i] = 0;
    if (tid == 0) { ints[0] = 0; ints[3] = 0; }
    __syncthreads();

    for (int i = tid; i < NC * KTOP; i += 256) {
        float v = row[i];
        if (v > 0.0f) atomicAdd(&fhist[__float_as_uint(v) >> 18], 1u);
    }
    __syncthreads();
    {
        int s = 0, base = tid * 16;
        #pragma unroll
        for (int k = 0; k < 16; k++) s += (int)fhist[base + k];
        fchunk[tid] = s;
    }
    __syncthreads();
    if (tid == 0) {
        int cum = 0, t0 = 0;
        for (int cc = 255; cc >= 0; cc--) {
            if (cum + fchunk[cc] >= MAXB) {
                int bk = cc * 16 + 15;
                for (;; bk--) { cum += (int)fhist[bk]; if (cum >= MAXB) break; }
                t0 = bk;
                break;
            }
            cum += fchunk[cc];
        }
        ints[1] = t0;   // stays 0 if < MAXB positive values (collect all)
    }
    __syncthreads();
    int t0 = ints[1];
    for (int i = tid; i < NC * KTOP; i += 256) {
        float v = row[i];
        unsigned bits = __float_as_uint(v);
        if (v > 0.0f && (bits >> 18) >= (unsigned)t0) {
            int p = atomicAdd(&ints[0], 1);
            if (p < FCAP) fkeys[p] = ((unsigned long long)bits << 32) | (unsigned)(~(unsigned)i);
        }
    }
    __syncthreads();
    int cnt = min(ints[0], FCAP);
    if (tid == 0) {
        int S = 128; while (S < cnt) S <<= 1;
        ints[2] = S;
    }
    __syncthreads();
    int S = ints[2];
    for (int i = cnt + tid; i < S; i += 256) fkeys[i] = 0ULL;
    __syncthreads();

    for (unsigned k = 2; k <= (unsigned)S; k <<= 1) {
        for (unsigned j = k >> 1; j > 0; j >>= 1) {
            for (unsigned i = tid; i < (unsigned)S; i += 256) {
                unsigned l = i ^ j;
                if (l > i) {
                    unsigned long long a = fkeys[i], bb = fkeys[l];
                    bool up = ((i & k) == 0);
                    if (up ? (a < bb) : (a > bb)) { fkeys[i] = bb; fkeys[l] = a; }
                }
            }
            __syncthreads();
        }
    }

    if (tid < MAXB) {
        unsigned long long wk = fkeys[tid];
        float val = __uint_as_float((unsigned)(wk >> 32));
        bool valid = (wk != 0ULL) && (val > 0.0f);
        float4 bx = make_float4(0.f, 0.f, 0.f, 0.f);
        float cls = 0.0f, sc = 0.0f;
        if (valid) {
            unsigned flat = ~(unsigned)wk;
            int c = (int)(flat >> 8);
            int k2 = (int)(flat & 255);
            float4 bb = g_cand_boxes4[((size_t)b * NC + c) * KTOP + k2];
            bx.x = fminf(fmaxf(bb.x, 0.0f), 1.0f);
            bx.y = fminf(fmaxf(bb.y, 0.0f), 1.0f);
            bx.z = fminf(fmaxf(bb.z, 0.0f), 1.0f);
            bx.w = fminf(fmaxf(bb.w, 0.0f), 1.0f);
            cls = (float)c;
            sc = val;
            atomicAdd(&ints[3], 1);
        }
        ((float4*)out)[b * MAXB + tid] = bx;                 // nb
        out[NB * 400 + b * MAXB + tid] = cls;                // nc
        out[NB * 500 + b * MAXB + tid] = sc;                 // ns
    }
    __syncthreads();
    if (tid == 0) out[NB * 600 + b] = (float)ints[3];        // num_detections
}

// ---------------- launch ----------------
extern "C" void kernel_launch(void* const* d_in, const int* in_sizes, int n_in,
                              void* d_out, int out_size)
{
    const float* x3 = (const float*)d_in[0];
    const float* x4 = (const float*)d_in[1];
    const float* x5 = (const float*)d_in[2];
    float* out = (float*)d_out;

    cudaFuncSetAttribute(topk_nms_kernel, cudaFuncAttributeMaxDynamicSharedMemorySize, TK_SMEM);

    decode_kernel<<<NB * 315, 256>>>(x3, x4, x5);
    topk_nms_kernel<<<NB * NC, 256, TK_SMEM>>>(x3, x4, x5);
    final_kernel<<<NB, 256>>>(out);
}

// round 3
// speedup vs baseline: 1.4611x; 1.2895x over previous
#include <cuda_runtime.h>
#include <cstdint>
#include <math.h>

#define NB 8
#define NC 80
#define NPTS 25200
#define KTOP 256
#define MAXB 100
#define NMS_T 0.6f
#define CAP 2048
#define FCAP 2048

// ---------------- scratch (static device globals) ----------------
__device__ float4 g_boxes4[NB * NPTS];                       // [B][N] yxyx
__device__ unsigned short g_key16[(size_t)NB * NC * NPTS];   // [B][C][N] approx key (smaller=better)
__device__ float4 g_cand_boxes4[NB * NC * KTOP];             // [B][C][K]
__device__ float  g_kept[NB * NC * KTOP];                    // [B][C][K]

__constant__ float c_anch[3][3][2] = {
    {{12.0f/640.0f, 16.0f/640.0f}, {19.0f/640.0f, 36.0f/640.0f}, {40.0f/640.0f, 28.0f/640.0f}},
    {{36.0f/640.0f, 75.0f/640.0f}, {76.0f/640.0f, 55.0f/640.0f}, {72.0f/640.0f, 146.0f/640.0f}},
    {{142.0f/640.0f,110.0f/640.0f},{192.0f/640.0f,243.0f/640.0f},{459.0f/640.0f,401.0f/640.0f}}};

__device__ __forceinline__ float sigm(float x) { return 1.0f / (1.0f + expf(-x)); }

// Schraudolph approx of e^{-x}: one-sided OVERestimate (<= +6.07% rel), monotone.
// Clamped so the resulting key d=(1+ea)(1+eb) is always finite, >= 1.0.
__device__ __forceinline__ float schr_em(float x) {
    float y = fmaf(x, -12102203.0f, 1065353216.0f);
    y = fminf(fmaxf(y, 0.0f), 2130706432.0f);   // [0, 0x7F000000]
    return __int_as_float((int)y);
}

// ---------------- Stage 1: decode (boxes exact; keys approx, FMA-only) ----------------
__global__ __launch_bounds__(256) void decode_kernel(
    const float* __restrict__ x3, const float* __restrict__ x4, const float* __restrict__ x5)
{
    __shared__ float sIn[6800];
    __shared__ float sEo1[80];      // 1 + ~e^{-obj}

    int blk = blockIdx.x;
    int b = blk / 315;
    int t = blk - b * 315;
    const float* src; int W, lvlOff, tloc, lvl;
    if (t < 240)      { lvl = 0; W = 80; lvlOff = 0;     tloc = t;       src = x3; }
    else if (t < 300) { lvl = 1; W = 40; lvlOff = 19200; tloc = t - 240; src = x4; }
    else              { lvl = 2; W = 20; lvlOff = 24000; tloc = t - 300; src = x5; }

    int tid = threadIdx.x;
    const float4* base4 = (const float4*)(src + (size_t)b * W * W * 255 + (size_t)tloc * 6800);
    for (int i = tid; i < 1700; i += 256) ((float4*)sIn)[i] = base4[i];
    __syncthreads();

    int nGlobBase = lvlOff + tloc * 80;
    float invW = 1.0f / (float)W;

    if (tid < 80) {
        const float* d = &sIn[tid * 85];
        int nLoc = tloc * 80 + tid;
        int a = nLoc % 3;
        int cell = nLoc / 3;
        int wq = cell % W;
        int hq = cell / W;
        float xc = (sigm(d[0]) + (float)wq) * invW;
        float yc = (sigm(d[1]) + (float)hq) * invW;
        float bw = expf(d[2]) * c_anch[lvl][a][0];
        float bh = expf(d[3]) * c_anch[lvl][a][1];
        float4 bx;
        bx.x = yc - bh * 0.5f;
        bx.y = xc - bw * 0.5f;
        bx.z = yc + bh * 0.5f;
        bx.w = xc + bw * 0.5f;
        g_boxes4[(size_t)b * NPTS + nGlobBase + tid] = bx;
        sEo1[tid] = 1.0f + schr_em(d[4]);
    }
    __syncthreads();

    if (tid < 160) {
        int q = tid % 20, cg = tid / 20;
        int a0 = q * 4;
        float e0 = sEo1[a0], e1 = sEo1[a0+1], e2 = sEo1[a0+2], e3 = sEo1[a0+3];
        const float* p = &sIn[a0 * 85 + 5 + cg];
        unsigned short* gp = g_key16 + ((size_t)b * NC + cg) * NPTS + nGlobBase + a0;
        #pragma unroll 2
        for (int j = 0; j < 10; j++) {
            float d0 = fmaf(schr_em(p[0]),   e0, e0);
            float d1 = fmaf(schr_em(p[85]),  e1, e1);
            float d2 = fmaf(schr_em(p[170]), e2, e2);
            float d3 = fmaf(schr_em(p[255]), e3, e3);
            unsigned lo = __byte_perm(__float_as_uint(d0), __float_as_uint(d1), 0x7632);
            unsigned hi = __byte_perm(__float_as_uint(d2), __float_as_uint(d3), 0x7632);
            *reinterpret_cast<uint2*>(gp) = make_uint2(lo, hi);
            p += 8;
            gp += (size_t)8 * NPTS;
        }
    }
}

// ---------------- helpers ----------------
__device__ __forceinline__ int cnt8le(uint4 v, unsigned m) {
    int s = 0;
    s += ((v.x & 0xffffu) <= m); s += ((v.x >> 16) <= m);
    s += ((v.y & 0xffffu) <= m); s += ((v.y >> 16) <= m);
    s += ((v.z & 0xffffu) <= m); s += ((v.z >> 16) <= m);
    s += ((v.w & 0xffffu) <= m); s += ((v.w >> 16) <= m);
    return s;
}

// Block-wide sum; NW warps, result broadcast to all threads. 2 syncthreads.
template <int NW>
__device__ __forceinline__ int blockSum(int v, int* red, int tid) {
    v += __shfl_down_sync(0xffffffffu, v, 16);
    v += __shfl_down_sync(0xffffffffu, v, 8);
    v += __shfl_down_sync(0xffffffffu, v, 4);
    v += __shfl_down_sync(0xffffffffu, v, 2);
    v += __shfl_down_sync(0xffffffffu, v, 1);
    if ((tid & 31) == 0) red[tid >> 5] = v;
    __syncthreads();
    int s = 0;
    #pragma unroll
    for (int w = 0; w < NW; w++) s += red[w];
    __syncthreads();
    return s;
}

// ---------------- Stage 2: fused top-256 select + exact rescore + sort + NMS ----------------
#define TK_SROW 0
#define TK_KEYS 50432
#define TK_CAND 66816
#define TK_RED  75008
#define TK_INTS 75040
#define TK_SMEM 75072
// overlays inside SROW (valid after candidate collection):
#define TK_Y0   0
#define TK_X0   1024
#define TK_Y1   2048
#define TK_X1   3072
#define TK_AR   4096
#define TK_MASK 5120

__global__ __launch_bounds__(256) void topk_nms_kernel(
    const float* __restrict__ x3, const float* __restrict__ x4, const float* __restrict__ x5)
{
    extern __shared__ char sm[];
    uint4* s4 = (uint4*)(sm + TK_SROW);
    unsigned long long* keys = (unsigned long long*)(sm + TK_KEYS);
    int* cand  = (int*)(sm + TK_CAND);
    int* red   = (int*)(sm + TK_RED);
    int* sInts = (int*)(sm + TK_INTS);     // 0:cnt

    int bc = blockIdx.x;
    int b = bc / NC, c = bc - b * NC;
    int tid = threadIdx.x;

    // ---- load key row to smem, fused with first count pass (pivot 0x4000 = d<=2.0) ----
    const uint4* r4 = (const uint4*)(g_key16 + (size_t)bc * NPTS);
    int cnt0 = 0;
    for (int i = tid; i < NPTS / 8; i += 256) {
        uint4 v = r4[i];
        s4[i] = v;
        cnt0 += cnt8le(v, 0x4000u);
    }
    __syncthreads();
    cnt0 = blockSum<8>(cnt0, red, tid);

    // ---- binary search for minimal T with count(key <= T) >= KTOP ----
    int lo, hi;
    if (cnt0 >= KTOP) { lo = 0x3F7F; hi = 0x4000; }
    else              { lo = 0x4000; hi = 0x7FFF; }
    while (hi - lo > 1) {
        int m = (lo + hi) >> 1;
        int cl = 0;
        for (int i = tid; i < NPTS / 8; i += 256) cl += cnt8le(s4[i], (unsigned)m);
        cl = blockSum<8>(cl, red, tid);
        if (cl >= KTOP) hi = m; else lo = m;
    }

    // margin: covers Schraudolph^2 (x1.1251) + 16-bit truncation both ways
    unsigned Tm = __float_as_uint(__uint_as_float((unsigned)hi << 16) * 1.15f) >> 16;
    if (Tm > 0x7FFFu) Tm = 0x7FFFu;

    // ---- collect candidates ----
    if (tid == 0) sInts[0] = 0;
    __syncthreads();
    for (int i = tid; i < NPTS / 8; i += 256) {
        uint4 v = s4[i]; int n0 = i * 8; unsigned k; int p;
        k = v.x & 0xffffu; if (k <= Tm) { p = atomicAdd(&sInts[0], 1); if (p < CAP) cand[p] = n0; }
        k = v.x >> 16;     if (k <= Tm) { p = atomicAdd(&sInts[0], 1); if (p < CAP) cand[p] = n0 + 1; }
        k = v.y & 0xffffu; if (k <= Tm) { p = atomicAdd(&sInts[0], 1); if (p < CAP) cand[p] = n0 + 2; }
        k = v.y >> 16;     if (k <= Tm) { p = atomicAdd(&sInts[0], 1); if (p < CAP) cand[p] = n0 + 3; }
        k = v.z & 0xffffu; if (k <= Tm) { p = atomicAdd(&sInts[0], 1); if (p < CAP) cand[p] = n0 + 4; }
        k = v.z >> 16;     if (k <= Tm) { p = atomicAdd(&sInts[0], 1); if (p < CAP) cand[p] = n0 + 5; }
        k = v.w & 0xffffu; if (k <= Tm) { p = atomicAdd(&sInts[0], 1); if (p < CAP) cand[p] = n0 + 6; }
        k = v.w >> 16;     if (k <= Tm) { p = atomicAdd(&sInts[0], 1); if (p < CAP) cand[p] = n0 + 7; }
    }
    __syncthreads();
    int cnt = sInts[0];
    if (cnt > CAP) {   // uniform fallback: strict threshold
        if (tid == 0) sInts[0] = 0;
        __syncthreads();
        unsigned Tb = (unsigned)hi;
        for (int i = tid; i < NPTS / 8; i += 256) {
            uint4 v = s4[i]; int n0 = i * 8; unsigned k; int p;
            k = v.x & 0xffffu; if (k <= Tb) { p = atomicAdd(&sInts[0], 1); if (p < CAP) cand[p] = n0; }
            k = v.x >> 16;     if (k <= Tb) { p = atomicAdd(&sInts[0], 1); if (p < CAP) cand[p] = n0 + 1; }
            k = v.y & 0xffffu; if (k <= Tb) { p = atomicAdd(&sInts[0], 1); if (p < CAP) cand[p] = n0 + 2; }
            k = v.y >> 16;     if (k <= Tb) { p = atomicAdd(&sInts[0], 1); if (p < CAP) cand[p] = n0 + 3; }
            k = v.z & 0xffffu; if (k <= Tb) { p = atomicAdd(&sInts[0], 1); if (p < CAP) cand[p] = n0 + 4; }
            k = v.z >> 16;     if (k <= Tb) { p = atomicAdd(&sInts[0], 1); if (p < CAP) cand[p] = n0 + 5; }
            k = v.w & 0xffffu; if (k <= Tb) { p = atomicAdd(&sInts[0], 1); if (p < CAP) cand[p] = n0 + 6; }
            k = v.w >> 16;     if (k <= Tb) { p = atomicAdd(&sInts[0], 1); if (p < CAP) cand[p] = n0 + 7; }
        }
        __syncthreads();
        cnt = min(sInts[0], CAP);
    }

    // ---- exact rescore of candidates ----
    for (int i = tid; i < cnt; i += 256) {
        int n = cand[i];
        const float* s;
        if (n < 19200)      s = x3 + (size_t)b * 1632000 + (size_t)n * 85;
        else if (n < 24000) s = x4 + (size_t)b * 408000  + (size_t)(n - 19200) * 85;
        else                s = x5 + (size_t)b * 102000  + (size_t)(n - 24000) * 85;
        float sc = sigm(s[5 + c]) * sigm(s[4]);
        keys[i] = ((unsigned long long)__float_as_uint(sc) << 32) | (unsigned)(~(unsigned)n);
    }
    int S = 256; while (S < cnt) S <<= 1;
    for (int i = cnt + tid; i < S; i += 256) keys[i] = 0ULL;
    __syncthreads();

    // ---- bitonic sort descending: (score desc, index asc via ~n) ----
    for (unsigned k = 2; k <= (unsigned)S; k <<= 1) {
        for (unsigned j = k >> 1; j > 0; j >>= 1) {
            for (unsigned i = tid; i < (unsigned)S; i += 256) {
                unsigned l = i ^ j;
                if (l > i) {
                    unsigned long long a = keys[i], bb = keys[l];
                    bool up = ((i & k) == 0);
                    if (up ? (a < bb) : (a > bb)) { keys[i] = bb; keys[l] = a; }
                }
            }
            __syncthreads();
        }
    }

    // ---- NMS on exact sorted top-256 (overlay arrays in dead srow space) ----
    float* sy0 = (float*)(sm + TK_Y0);
    float* sx0 = (float*)(sm + TK_X0);
    float* sy1 = (float*)(sm + TK_Y1);
    float* sx1 = (float*)(sm + TK_X1);
    float* sar = (float*)(sm + TK_AR);
    unsigned* smask = (unsigned*)(sm + TK_MASK);

    unsigned long long key = keys[tid];
    float val = __uint_as_float((unsigned)(key >> 32));
    unsigned n = ~(unsigned)key;
    float4 bb4 = g_boxes4[(size_t)b * NPTS + n];
    g_cand_boxes4[(size_t)bc * KTOP + tid] = bb4;
    sy0[tid] = bb4.x; sx0[tid] = bb4.y; sy1[tid] = bb4.z; sx1[tid] = bb4.w;
    float ar = (bb4.z - bb4.x) * (bb4.w - bb4.y);
    sar[tid] = ar;
    __syncthreads();

    unsigned m[8];
    #pragma unroll
    for (int w = 0; w < 8; w++) m[w] = 0;
    float y0 = bb4.x, x0 = bb4.y, y1 = bb4.z, x1 = bb4.w;
    for (int j = 0; j < KTOP; ++j) {
        if (j > tid) {
            float iy = fmaxf(fminf(y1, sy1[j]) - fmaxf(y0, sy0[j]), 0.0f);
            float ix = fmaxf(fminf(x1, sx1[j]) - fmaxf(x0, sx0[j]), 0.0f);
            float inter = iy * ix;
            float uni = ar + sar[j] - inter;
            if (inter > NMS_T * fmaxf(uni, 1e-9f)) m[j >> 5] |= (1u << (j & 31));
        }
    }
    #pragma unroll
    for (int w = 0; w < 8; w++) smask[tid * 8 + w] = m[w];
    __syncthreads();

    if (tid == 0) {
        unsigned kp[8];
        #pragma unroll
        for (int w = 0; w < 8; w++) kp[w] = 0xFFFFFFFFu;
        for (int i = 0; i < KTOP; ++i) {
            if ((kp[i >> 5] >> (i & 31)) & 1u) {
                #pragma unroll
                for (int w = 0; w < 8; w++) kp[w] &= ~smask[i * 8 + w];
            }
        }
        #pragma unroll
        for (int w = 0; w < 8; w++) red[w] = (int)kp[w];
    }
    __syncthreads();

    bool keep = ((unsigned)red[tid >> 5] >> (tid & 31)) & 1u;
    g_kept[(size_t)bc * KTOP + tid] = keep ? val : 0.0f;
}

// ---------------- Stage 3: per-image top-100 (counting select + exact sort) ----------------
#define F_VAL  0
#define F_KEYS 81920
#define F_RED  98304
#define F_INTS 98368
#define F_SMEM 98432

__global__ __launch_bounds__(512) void final_kernel(float* __restrict__ out)
{
    extern __shared__ char fsm[];
    uint4* v4 = (uint4*)(fsm + F_VAL);                           // 20480 floats as bits
    unsigned long long* fkeys = (unsigned long long*)(fsm + F_KEYS);
    int* red  = (int*)(fsm + F_RED);
    int* ints = (int*)(fsm + F_INTS);   // 0:cnt 1:numdet

    int b = blockIdx.x, tid = threadIdx.x;
    const uint4* row4 = (const uint4*)(g_kept + (size_t)b * NC * KTOP);

    // load + count positives
    int cpos = 0;
    for (int i = tid; i < NC * KTOP / 4; i += 512) {
        uint4 v = row4[i];
        v4[i] = v;
        cpos += (v.x >= 1u) + (v.y >= 1u) + (v.z >= 1u) + (v.w >= 1u);
    }
    __syncthreads();
    cpos = blockSum<16>(cpos, red, tid);

    // binary search on top-16 float bits: max t with count(bits>>16 >= t) >= MAXB
    int t16 = 0;
    if (cpos >= MAXB) {
        int lo = 0, hi = 0x3F81;      // scores < 1.0
        while (hi - lo > 1) {
            int m = (lo + hi) >> 1;
            unsigned mb = (unsigned)m << 16;
            int cl = 0;
            for (int i = tid; i < NC * KTOP / 4; i += 512) {
                uint4 v = v4[i];
                cl += (v.x >= mb) + (v.y >= mb) + (v.z >= mb) + (v.w >= mb);
            }
            cl = blockSum<16>(cl, red, tid);
            if (cl >= MAXB) lo = m; else hi = m;
        }
        t16 = lo;
    }
    unsigned Tb = (unsigned)t16 << 16;
    if (Tb < 1u) Tb = 1u;            // exclude zeros (suppressed)

    if (tid == 0) { ints[0] = 0; ints[1] = 0; }
    __syncthreads();
    for (int i = tid; i < NC * KTOP / 4; i += 512) {
        uint4 v = v4[i]; int n0 = i * 4; int p;
        if (v.x >= Tb) { p = atomicAdd(&ints[0], 1); if (p < FCAP) fkeys[p] = ((unsigned long long)v.x << 32) | (unsigned)(~(unsigned)n0); }
        if (v.y >= Tb) { p = atomicAdd(&ints[0], 1); if (p < FCAP) fkeys[p] = ((unsigned long long)v.y << 32) | (unsigned)(~(unsigned)(n0+1)); }
        if (v.z >= Tb) { p = atomicAdd(&ints[0], 1); if (p < FCAP) fkeys[p] = ((unsigned long long)v.z << 32) | (unsigned)(~(unsigned)(n0+2)); }
        if (v.w >= Tb) { p = atomicAdd(&ints[0], 1); if (p < FCAP) fkeys[p] = ((unsigned long long)v.w << 32) | (unsigned)(~(unsigned)(n0+3)); }
    }
    __syncthreads();
    int cnt = min(ints[0], FCAP);
    int S = 128; while (S < cnt) S <<= 1;
    for (int i = cnt + tid; i < S; i += 512) fkeys[i] = 0ULL;
    __syncthreads();

    for (unsigned k = 2; k <= (unsigned)S; k <<= 1) {
        for (unsigned j = k >> 1; j > 0; j >>= 1) {
            for (unsigned i = tid; i < (unsigned)S; i += 512) {
                unsigned l = i ^ j;
                if (l > i) {
                    unsigned long long a = fkeys[i], bb = fkeys[l];
                    bool up = ((i & k) == 0);
                    if (up ? (a < bb) : (a > bb)) { fkeys[i] = bb; fkeys[l] = a; }
                }
            }
            __syncthreads();
        }
    }

    if (tid < MAXB) {
        unsigned long long wk = fkeys[tid];
        float val = __uint_as_float((unsigned)(wk >> 32));
        bool valid = (wk != 0ULL) && (val > 0.0f);
        float4 bx = make_float4(0.f, 0.f, 0.f, 0.f);
        float cls = 0.0f, sc = 0.0f;
        if (valid) {
            unsigned flat = ~(unsigned)wk;
            int c = (int)(flat >> 8);
            int k2 = (int)(flat & 255);
            float4 bb = g_cand_boxes4[((size_t)b * NC + c) * KTOP + k2];
            bx.x = fminf(fmaxf(bb.x, 0.0f), 1.0f);
            bx.y = fminf(fmaxf(bb.y, 0.0f), 1.0f);
            bx.z = fminf(fmaxf(bb.z, 0.0f), 1.0f);
            bx.w = fminf(fmaxf(bb.w, 0.0f), 1.0f);
            cls = (float)c;
            sc = val;
            atomicAdd(&ints[1], 1);
        }
        ((float4*)out)[b * MAXB + tid] = bx;                 // nb
        out[NB * 400 + b * MAXB + tid] = cls;                // nc
        out[NB * 500 + b * MAXB + tid] = sc;                 // ns
    }
    __syncthreads();
    if (tid == 0) out[NB * 600 + b] = (float)ints[1];        // num_detections
}

// ---------------- launch ----------------
extern "C" void kernel_launch(void* const* d_in, const int* in_sizes, int n_in,
                              void* d_out, int out_size)
{
    const float* x3 = (const float*)d_in[0];
    const float* x4 = (const float*)d_in[1];
    const float* x5 = (const float*)d_in[2];
    float* out = (float*)d_out;

    cudaFuncSetAttribute(topk_nms_kernel, cudaFuncAttributeMaxDynamicSharedMemorySize, TK_SMEM);
    cudaFuncSetAttribute(final_kernel, cudaFuncAttributeMaxDynamicSharedMemorySize, F_SMEM);

    decode_kernel<<<NB * 315, 256>>>(x3, x4, x5);
    topk_nms_kernel<<<NB * NC, 256, TK_SMEM>>>(x3, x4, x5);
    final_kernel<<<NB, 512, F_SMEM>>>(out);
}

// round 5
// speedup vs baseline: 1.6712x; 1.1438x over previous
#include <cuda_runtime.h>
#include <cstdint>
#include <math.h>

#define NB 8
#define NC 80
#define NPTS 25200
#define KTOP 256
#define MAXB 100
#define NMS_T 0.6f
#define CAP 2048
#define FCAP 2048

typedef unsigned long long u64;

// ---------------- scratch (static device globals) ----------------
__device__ float4 g_boxes4[NB * NPTS];                       // [B][N] yxyx
__device__ unsigned short g_key16[(size_t)NB * NC * NPTS];   // [B][C][N] approx key (smaller=better)
__device__ float4 g_cand_boxes4[NB * NC * KTOP];             // [B][C][K]
__device__ float  g_kept[NB * NC * KTOP];                    // [B][C][K]

__constant__ float c_anch[3][3][2] = {
    {{12.0f/640.0f, 16.0f/640.0f}, {19.0f/640.0f, 36.0f/640.0f}, {40.0f/640.0f, 28.0f/640.0f}},
    {{36.0f/640.0f, 75.0f/640.0f}, {76.0f/640.0f, 55.0f/640.0f}, {72.0f/640.0f, 146.0f/640.0f}},
    {{142.0f/640.0f,110.0f/640.0f},{192.0f/640.0f,243.0f/640.0f},{459.0f/640.0f,401.0f/640.0f}}};

__device__ __forceinline__ float sigm(float x) { return 1.0f / (1.0f + expf(-x)); }

// Schraudolph approx of e^{-x}: one-sided OVERestimate (<= +6.07% rel), monotone.
__device__ __forceinline__ float schr_em(float x) {
    float y = fmaf(x, -12102203.0f, 1065353216.0f);
    y = fminf(fmaxf(y, 0.0f), 2130706432.0f);   // [0, 0x7F000000]
    return __int_as_float((int)y);
}

// ---------------- Stage 1: decode (boxes exact; keys approx, FMA-only) ----------------
__global__ __launch_bounds__(256) void decode_kernel(
    const float* __restrict__ x3, const float* __restrict__ x4, const float* __restrict__ x5)
{
    __shared__ float sIn[6800];
    __shared__ float sEo1[80];      // 1 + ~e^{-obj}

    int blk = blockIdx.x;
    int b = blk / 315;
    int t = blk - b * 315;
    const float* src; int W, lvlOff, tloc, lvl;
    if (t < 240)      { lvl = 0; W = 80; lvlOff = 0;     tloc = t;       src = x3; }
    else if (t < 300) { lvl = 1; W = 40; lvlOff = 19200; tloc = t - 240; src = x4; }
    else              { lvl = 2; W = 20; lvlOff = 24000; tloc = t - 300; src = x5; }

    int tid = threadIdx.x;
    const float4* base4 = (const float4*)(src + (size_t)b * W * W * 255 + (size_t)tloc * 6800);
    for (int i = tid; i < 1700; i += 256) ((float4*)sIn)[i] = base4[i];
    __syncthreads();

    int nGlobBase = lvlOff + tloc * 80;
    float invW = 1.0f / (float)W;

    if (tid < 80) {
        const float* d = &sIn[tid * 85];
        int nLoc = tloc * 80 + tid;
        int a = nLoc % 3;
        int cell = nLoc / 3;
        int wq = cell % W;
        int hq = cell / W;
        float xc = (sigm(d[0]) + (float)wq) * invW;
        float yc = (sigm(d[1]) + (float)hq) * invW;
        float bw = expf(d[2]) * c_anch[lvl][a][0];
        float bh = expf(d[3]) * c_anch[lvl][a][1];
        float4 bx;
        bx.x = yc - bh * 0.5f;
        bx.y = xc - bw * 0.5f;
        bx.z = yc + bh * 0.5f;
        bx.w = xc + bw * 0.5f;
        g_boxes4[(size_t)b * NPTS + nGlobBase + tid] = bx;
        sEo1[tid] = 1.0f + schr_em(d[4]);
    }
    __syncthreads();

    if (tid < 160) {
        int q = tid % 20, cg = tid / 20;
        int a0 = q * 4;
        float e0 = sEo1[a0], e1 = sEo1[a0+1], e2 = sEo1[a0+2], e3 = sEo1[a0+3];
        const float* p = &sIn[a0 * 85 + 5 + cg];
        unsigned short* gp = g_key16 + ((size_t)b * NC + cg) * NPTS + nGlobBase + a0;
        #pragma unroll 2
        for (int j = 0; j < 10; j++) {
            float d0 = fmaf(schr_em(p[0]),   e0, e0);
            float d1 = fmaf(schr_em(p[85]),  e1, e1);
            float d2 = fmaf(schr_em(p[170]), e2, e2);
            float d3 = fmaf(schr_em(p[255]), e3, e3);
            unsigned lo = __byte_perm(__float_as_uint(d0), __float_as_uint(d1), 0x7632);
            unsigned hi = __byte_perm(__float_as_uint(d2), __float_as_uint(d3), 0x7632);
            *reinterpret_cast<uint2*>(gp) = make_uint2(lo, hi);
            p += 8;
            gp += (size_t)8 * NPTS;
        }
    }
}

// ---------------- helpers ----------------
__device__ __forceinline__ int cnt8le(uint4 v, unsigned m) {
    int s = 0;
    s += ((v.x & 0xffffu) <= m); s += ((v.x >> 16) <= m);
    s += ((v.y & 0xffffu) <= m); s += ((v.y >> 16) <= m);
    s += ((v.z & 0xffffu) <= m); s += ((v.z >> 16) <= m);
    s += ((v.w & 0xffffu) <= m); s += ((v.w >> 16) <= m);
    return s;
}

template <int NW>
__device__ __forceinline__ int blockSum(int v, int* red, int tid) {
    v += __shfl_down_sync(0xffffffffu, v, 16);
    v += __shfl_down_sync(0xffffffffu, v, 8);
    v += __shfl_down_sync(0xffffffffu, v, 4);
    v += __shfl_down_sync(0xffffffffu, v, 2);
    v += __shfl_down_sync(0xffffffffu, v, 1);
    __syncthreads();
    if ((tid & 31) == 0) red[tid >> 5] = v;
    __syncthreads();
    int s = 0;
    #pragma unroll
    for (int w = 0; w < NW; w++) s += red[w];
    return s;
}

__device__ __forceinline__ u64 rescore_key(
    int b, int c, int n,
    const float* __restrict__ x3, const float* __restrict__ x4, const float* __restrict__ x5)
{
    const float* s;
    if (n < 19200)      s = x3 + (size_t)b * 1632000 + (size_t)n * 85;
    else if (n < 24000) s = x4 + (size_t)b * 408000  + (size_t)(n - 19200) * 85;
    else                s = x5 + (size_t)b * 102000  + (size_t)(n - 24000) * 85;
    float sc = sigm(s[5 + c]) * sigm(s[4]);
    return ((u64)__float_as_uint(sc) << 32) | (unsigned)(~(unsigned)n);
}

// ---------------- Stage 2: top-256 select + exact rescore + sort + NMS ----------------
// smem: kA[2048] u64 @0 (16KB), kB[2048] u64 @16384 (16KB), red @32768, sInts @32800
// NMS overlays in kA region after compact: y0@0 x0@1024 y1@2048 x1@3072 ar@4096 mask@5120
#define TK_SMEM 32832

__global__ __launch_bounds__(256) void topk_nms_kernel(
    const float* __restrict__ x3, const float* __restrict__ x4, const float* __restrict__ x5)
{
    extern __shared__ char sm[];
    u64* kA = (u64*)sm;
    u64* kB = (u64*)(sm + 16384);
    int* red   = (int*)(sm + 32768);
    int* sInts = (int*)(sm + 32800);

    int bc = blockIdx.x;
    int b = bc / NC, c = bc - b * NC;
    int tid = threadIdx.x;
    const uint4* r4 = (const uint4*)(g_key16 + (size_t)bc * NPTS);

    // ---- counting pass over global (L2-resident) keys ----
    auto countpass = [&](unsigned m) -> int {
        int cl = 0;
        for (int i = tid; i < NPTS / 8; i += 256) cl += cnt8le(__ldg(&r4[i]), m);
        return blockSum<8>(cl, red, tid);
    };

    // ---- early-exit binary search: any T with KTOP <= cnt(T) (<= 512 preferred) ----
    int lo = 0x3F7F, hi = 0x7FFF;
    bool found = false;
    {
        int m = 0x4000;                      // score 0.5 first probe
        int cl = countpass((unsigned)m);
        if (cl >= KTOP) { hi = m; found = (cl <= 512); }
        else lo = m;
    }
    while (!found && hi - lo > 1) {
        int m = (lo + hi) >> 1;
        int cl = countpass((unsigned)m);
        if (cl >= KTOP) { hi = m; found = (cl <= 512); }
        else lo = m;
    }

    // ---- margin collect + fused exact rescore ----
    auto collect = [&](unsigned Tm) -> int {
        __syncthreads();
        if (tid == 0) sInts[0] = 0;
        __syncthreads();
        for (int i = tid; i < NPTS / 8; i += 256) {
            uint4 v = __ldg(&r4[i]);
            int n0 = i * 8;
            unsigned ks[8] = { v.x & 0xffffu, v.x >> 16, v.y & 0xffffu, v.y >> 16,
                               v.z & 0xffffu, v.z >> 16, v.w & 0xffffu, v.w >> 16 };
            #pragma unroll
            for (int e = 0; e < 8; e++) {
                if (ks[e] <= Tm) {
                    int p = atomicAdd(&sInts[0], 1);
                    if (p < CAP) kA[p] = rescore_key(b, c, n0 + e, x3, x4, x5);
                }
            }
        }
        __syncthreads();
        return sInts[0];
    };

    auto margin_of = [](int T0) -> unsigned {
        unsigned Tm = __float_as_uint(__uint_as_float((unsigned)T0 << 16) * 1.15f) >> 16;
        return Tm > 0x7FFFu ? 0x7FFFu : Tm;
    };

    int cnt = collect(margin_of(hi));
    if (cnt > CAP) {
        // rare: finish search to minimal threshold, retry with margin, then strict
        while (hi - lo > 1) {
            int m = (lo + hi) >> 1;
            int cl = countpass((unsigned)m);
            if (cl >= KTOP) hi = m; else lo = m;
        }
        cnt = collect(margin_of(hi));
        if (cnt > CAP) cnt = collect((unsigned)hi);
    }
    if (cnt > CAP) cnt = CAP;

    // ---- trim by exact score: find max t16 with count(top16(score) >= t16) >= KTOP ----
    auto count16 = [&](unsigned t) -> int {
        int cl = 0;
        for (int i = tid; i < cnt; i += 256) cl += ((unsigned)(kA[i] >> 48) >= t);
        return blockSum<8>(cl, red, tid);
    };
    int tlo = 0, thi = 0x3F81;
    bool tfound = false;
    while (!tfound && thi - tlo > 1) {
        int m = (tlo + thi) >> 1;
        int cl = count16((unsigned)m);
        if (cl >= KTOP) { tlo = m; tfound = (cl <= 448); }
        else thi = m;
    }
    unsigned t16 = (unsigned)tlo;

    // compact survivors into kB
    __syncthreads();
    if (tid == 0) sInts[0] = 0;
    __syncthreads();
    for (int i = tid; i < cnt; i += 256) {
        u64 k = kA[i];
        if ((unsigned)(k >> 48) >= t16) {
            int p = atomicAdd(&sInts[0], 1);
            if (p < CAP) kB[p] = k;
        }
    }
    __syncthreads();
    int cnt2 = min(sInts[0], CAP);
    int S = 256; while (S < cnt2) S <<= 1;
    for (int i = cnt2 + tid; i < S; i += 256) kB[i] = 0ULL;
    __syncthreads();

    // ---- bitonic sort descending (score desc, index asc via ~n) ----
    for (unsigned k = 2; k <= (unsigned)S; k <<= 1) {
        for (unsigned j = k >> 1; j > 0; j >>= 1) {
            for (unsigned i = tid; i < (unsigned)S; i += 256) {
                unsigned l = i ^ j;
                if (l > i) {
                    u64 a = kB[i], bb = kB[l];
                    bool up = ((i & k) == 0);
                    if (up ? (a < bb) : (a > bb)) { kB[i] = bb; kB[l] = a; }
                }
            }
            __syncthreads();
        }
    }

    // ---- NMS on exact sorted top-256 (overlay arrays in dead kA space) ----
    float* sy0 = (float*)(sm + 0);
    float* sx0 = (float*)(sm + 1024);
    float* sy1 = (float*)(sm + 2048);
    float* sx1 = (float*)(sm + 3072);
    float* sar = (float*)(sm + 4096);
    unsigned* smask = (unsigned*)(sm + 5120);   // [256][8]

    u64 key = kB[tid];
    float val = __uint_as_float((unsigned)(key >> 32));
    unsigned n = ~(unsigned)key;
    float4 bb4 = g_boxes4[(size_t)b * NPTS + n];
    g_cand_boxes4[(size_t)bc * KTOP + tid] = bb4;
    sy0[tid] = bb4.x; sx0[tid] = bb4.y; sy1[tid] = bb4.z; sx1[tid] = bb4.w;
    float ar = (bb4.z - bb4.x) * (bb4.w - bb4.y);
    sar[tid] = ar;
    __syncthreads();

    unsigned m8[8];
    #pragma unroll
    for (int w = 0; w < 8; w++) m8[w] = 0;
    float y0 = bb4.x, x0 = bb4.y, y1 = bb4.z, x1 = bb4.w;
    int jstart = tid & ~31;          // warp-uniform start; predicate j>tid inside
    for (int j = jstart; j < KTOP; ++j) {
        if (j > tid) {
            float iy = fmaxf(fminf(y1, sy1[j]) - fmaxf(y0, sy0[j]), 0.0f);
            float ix = fmaxf(fminf(x1, sx1[j]) - fmaxf(x0, sx0[j]), 0.0f);
            float inter = iy * ix;
            float uni = ar + sar[j] - inter;
            if (inter > NMS_T * fmaxf(uni, 1e-9f)) m8[j >> 5] |= (1u << (j & 31));
        }
    }
    #pragma unroll
    for (int w = 0; w < 8; w++) smask[tid * 8 + w] = m8[w];
    __syncthreads();

    // warp-parallel greedy suppression scan (warp 0)
    if (tid < 32) {
        unsigned kp = 0xFFFFFFFFu;         // lane w<8 owns keep word w
        for (int i = 0; i < KTOP; ++i) {
            unsigned kw = __shfl_sync(0xffffffffu, kp, i >> 5);
            bool alive = (kw >> (i & 31)) & 1u;
            if (alive && tid < 8) kp &= ~smask[i * 8 + tid];
        }
        if (tid < 8) red[tid] = (int)kp;
    }
    __syncthreads();

    bool keep = ((unsigned)red[tid >> 5] >> (tid & 31)) & 1u;
    g_kept[(size_t)bc * KTOP + tid] = keep ? val : 0.0f;
}

// ---------------- Stage 3: per-image top-100 (counting select + exact sort) ----------------
#define F_VAL  0
#define F_KEYS 81920
#define F_RED  98304
#define F_INTS 98432
#define F_SMEM 98448

__global__ __launch_bounds__(1024) void final_kernel(float* __restrict__ out)
{
    extern __shared__ char fsm[];
    uint4* v4 = (uint4*)(fsm + F_VAL);                         // 20480 floats as bits
    u64* fkeys = (u64*)(fsm + F_KEYS);
    int* red  = (int*)(fsm + F_RED);
    int* ints = (int*)(fsm + F_INTS);   // 0:cnt 1:numdet

    int b = blockIdx.x, tid = threadIdx.x;
    const uint4* row4 = (const uint4*)(g_kept + (size_t)b * NC * KTOP);

    int cpos = 0;
    for (int i = tid; i < NC * KTOP / 4; i += 1024) {
        uint4 v = row4[i];
        v4[i] = v;
        cpos += (v.x >= 1u) + (v.y >= 1u) + (v.z >= 1u) + (v.w >= 1u);
    }
    __syncthreads();
    cpos = blockSum<32>(cpos, red, tid);

    // early-exit search: max t with count(bits>>16 >= t) >= MAXB (prefer <= 256)
    int t16 = 0;
    if (cpos >= MAXB) {
        int lo = 0, hi = 0x3F81;
        bool found = false;
        while (!found && hi - lo > 1) {
            int m = (lo + hi) >> 1;
            unsigned mb = (unsigned)m << 16;
            int cl = 0;
            for (int i = tid; i < NC * KTOP / 4; i += 1024) {
                uint4 v = v4[i];
                cl += (v.x >= mb) + (v.y >= mb) + (v.z >= mb) + (v.w >= mb);
            }
            cl = blockSum<32>(cl, red, tid);
            if (cl >= MAXB) { lo = m; found = (cl <= 256); }
            else hi = m;
        }
        t16 = lo;
    }
    unsigned Tb = (unsigned)t16 << 16;
    if (Tb < 1u) Tb = 1u;            // exclude zeros (suppressed)

    __syncthreads();
    if (tid == 0) { ints[0] = 0; ints[1] = 0; }
    __syncthreads();
    for (int i = tid; i < NC * KTOP / 4; i += 1024) {
        uint4 v = v4[i]; int n0 = i * 4; int p;
        if (v.x >= Tb) { p = atomicAdd(&ints[0], 1); if (p < FCAP) fkeys[p] = ((u64)v.x << 32) | (unsigned)(~(unsigned)n0); }
        if (v.y >= Tb) { p = atomicAdd(&ints[0], 1); if (p < FCAP) fkeys[p] = ((u64)v.y << 32) | (unsigned)(~(unsigned)(n0+1)); }
        if (v.z >= Tb) { p = atomicAdd(&ints[0], 1); if (p < FCAP) fkeys[p] = ((u64)v.z << 32) | (unsigned)(~(unsigned)(n0+2)); }
        if (v.w >= Tb) { p = atomicAdd(&ints[0], 1); if (p < FCAP) fkeys[p] = ((u64)v.w << 32) | (unsigned)(~(unsigned)(n0+3)); }
    }
    __syncthreads();
    int cnt = min(ints[0], FCAP);
    int S = 128; while (S < cnt) S <<= 1;
    for (int i = cnt + tid; i < S; i += 1024) fkeys[i] = 0ULL;
    __syncthreads();

    for (unsigned k = 2; k <= (unsigned)S; k <<= 1) {
        for (unsigned j = k >> 1; j > 0; j >>= 1) {
            for (unsigned i = tid; i < (unsigned)S; i += 1024) {
                unsigned l = i ^ j;
                if (l > i) {
                    u64 a = fkeys[i], bb = fkeys[l];
                    bool up = ((i & k) == 0);
                    if (up ? (a < bb) : (a > bb)) { fkeys[i] = bb; fkeys[l] = a; }
                }
            }
            __syncthreads();
        }
    }

    if (tid < MAXB) {
        u64 wk = fkeys[tid];
        float val = __uint_as_float((unsigned)(wk >> 32));
        bool valid = (wk != 0ULL) && (val > 0.0f);
        float4 bx = make_float4(0.f, 0.f, 0.f, 0.f);
        float cls = 0.0f, sc = 0.0f;
        if (valid) {
            unsigned flat = ~(unsigned)wk;
            int c = (int)(flat >> 8);
            int k2 = (int)(flat & 255);
            float4 bb = g_cand_boxes4[((size_t)b * NC + c) * KTOP + k2];
            bx.x = fminf(fmaxf(bb.x, 0.0f), 1.0f);
            bx.y = fminf(fmaxf(bb.y, 0.0f), 1.0f);
            bx.z = fminf(fmaxf(bb.z, 0.0f), 1.0f);
            bx.w = fminf(fmaxf(bb.w, 0.0f), 1.0f);
            cls = (float)c;
            sc = val;
            atomicAdd(&ints[1], 1);
        }
        ((float4*)out)[b * MAXB + tid] = bx;                 // nb
        out[NB * 400 + b * MAXB + tid] = cls;                // nc
        out[NB * 500 + b * MAXB + tid] = sc;                 // ns
    }
    __syncthreads();
    if (tid == 0) out[NB * 600 + b] = (float)ints[1];        // num_detections
}

// ---------------- launch ----------------
extern "C" void kernel_launch(void* const* d_in, const int* in_sizes, int n_in,
                              void* d_out, int out_size)
{
    const float* x3 = (const float*)d_in[0];
    const float* x4 = (const float*)d_in[1];
    const float* x5 = (const float*)d_in[2];
    float* out = (float*)d_out;

    cudaFuncSetAttribute(topk_nms_kernel, cudaFuncAttributeMaxDynamicSharedMemorySize, TK_SMEM);
    cudaFuncSetAttribute(final_kernel, cudaFuncAttributeMaxDynamicSharedMemorySize, F_SMEM);

    decode_kernel<<<NB * 315, 256>>>(x3, x4, x5);
    topk_nms_kernel<<<NB * NC, 256, TK_SMEM>>>(x3, x4, x5);
    final_kernel<<<NB, 1024, F_SMEM>>>(out);
}

// round 6
// speedup vs baseline: 1.9483x; 1.1658x over previous
#include <cuda_runtime.h>
#include <cstdint>
#include <math.h>

#define NB 8
#define NC 80
#define NPTS 25200
#define KTOP 256
#define MAXB 100
#define NMS_T 0.6f
#define CAP 2048
#define FCAP 2048

typedef unsigned long long u64;

// ---------------- scratch (static device globals) ----------------
__device__ float4 g_boxes4[NB * NPTS];                       // [B][N] yxyx
__device__ unsigned short g_key16[(size_t)NB * NC * NPTS];   // [B][C][N] approx key (smaller=better)
__device__ float4 g_cand_boxes4[NB * NC * KTOP];             // [B][C][K]
__device__ float  g_kept[NB * NC * KTOP];                    // [B][C][K]

__constant__ float c_anch[3][3][2] = {
    {{12.0f/640.0f, 16.0f/640.0f}, {19.0f/640.0f, 36.0f/640.0f}, {40.0f/640.0f, 28.0f/640.0f}},
    {{36.0f/640.0f, 75.0f/640.0f}, {76.0f/640.0f, 55.0f/640.0f}, {72.0f/640.0f, 146.0f/640.0f}},
    {{142.0f/640.0f,110.0f/640.0f},{192.0f/640.0f,243.0f/640.0f},{459.0f/640.0f,401.0f/640.0f}}};

__device__ __forceinline__ float sigm(float x) { return 1.0f / (1.0f + expf(-x)); }

// Schraudolph approx of e^{-x}: one-sided OVERestimate (<= +6.07% rel), monotone.
__device__ __forceinline__ float schr_em(float x) {
    float y = fmaf(x, -12102203.0f, 1065353216.0f);
    y = fminf(fmaxf(y, 0.0f), 2130706432.0f);   // [0, 0x7F000000]
    return __int_as_float((int)y);
}

// ---------------- Stage 1: decode (boxes exact; keys approx, FMA-only) ----------------
__global__ __launch_bounds__(256) void decode_kernel(
    const float* __restrict__ x3, const float* __restrict__ x4, const float* __restrict__ x5)
{
    __shared__ float sIn[6800];
    __shared__ float sEo1[80];      // 1 + ~e^{-obj}

    int blk = blockIdx.x;
    int b = blk / 315;
    int t = blk - b * 315;
    const float* src; int W, lvlOff, tloc, lvl;
    if (t < 240)      { lvl = 0; W = 80; lvlOff = 0;     tloc = t;       src = x3; }
    else if (t < 300) { lvl = 1; W = 40; lvlOff = 19200; tloc = t - 240; src = x4; }
    else              { lvl = 2; W = 20; lvlOff = 24000; tloc = t - 300; src = x5; }

    int tid = threadIdx.x;
    const float4* base4 = (const float4*)(src + (size_t)b * W * W * 255 + (size_t)tloc * 6800);
    for (int i = tid; i < 1700; i += 256) ((float4*)sIn)[i] = base4[i];
    __syncthreads();

    int nGlobBase = lvlOff + tloc * 80;
    float invW = 1.0f / (float)W;

    if (tid < 80) {
        const float* d = &sIn[tid * 85];
        int nLoc = tloc * 80 + tid;
        int a = nLoc % 3;
        int cell = nLoc / 3;
        int wq = cell % W;
        int hq = cell / W;
        float xc = (sigm(d[0]) + (float)wq) * invW;
        float yc = (sigm(d[1]) + (float)hq) * invW;
        float bw = expf(d[2]) * c_anch[lvl][a][0];
        float bh = expf(d[3]) * c_anch[lvl][a][1];
        float4 bx;
        bx.x = yc - bh * 0.5f;
        bx.y = xc - bw * 0.5f;
        bx.z = yc + bh * 0.5f;
        bx.w = xc + bw * 0.5f;
        g_boxes4[(size_t)b * NPTS + nGlobBase + tid] = bx;
        sEo1[tid] = 1.0f + schr_em(d[4]);
    }
    __syncthreads();

    if (tid < 160) {
        int q = tid % 20, cg = tid / 20;
        int a0 = q * 4;
        float e0 = sEo1[a0], e1 = sEo1[a0+1], e2 = sEo1[a0+2], e3 = sEo1[a0+3];
        const float* p = &sIn[a0 * 85 + 5 + cg];
        unsigned short* gp = g_key16 + ((size_t)b * NC + cg) * NPTS + nGlobBase + a0;
        #pragma unroll 2
        for (int j = 0; j < 10; j++) {
            float d0 = fmaf(schr_em(p[0]),   e0, e0);
            float d1 = fmaf(schr_em(p[85]),  e1, e1);
            float d2 = fmaf(schr_em(p[170]), e2, e2);
            float d3 = fmaf(schr_em(p[255]), e3, e3);
            unsigned lo = __byte_perm(__float_as_uint(d0), __float_as_uint(d1), 0x7632);
            unsigned hi = __byte_perm(__float_as_uint(d2), __float_as_uint(d3), 0x7632);
            *reinterpret_cast<uint2*>(gp) = make_uint2(lo, hi);
            p += 8;
            gp += (size_t)8 * NPTS;
        }
    }
}

// ---------------- helpers ----------------
__device__ __forceinline__ int cnt8le(uint4 v, unsigned m) {
    int s = 0;
    s += ((v.x & 0xffffu) <= m); s += ((v.x >> 16) <= m);
    s += ((v.y & 0xffffu) <= m); s += ((v.y >> 16) <= m);
    s += ((v.z & 0xffffu) <= m); s += ((v.z >> 16) <= m);
    s += ((v.w & 0xffffu) <= m); s += ((v.w >> 16) <= m);
    return s;
}

template <int NW>
__device__ __forceinline__ int blockSum(int v, int* red, int tid) {
    v += __shfl_down_sync(0xffffffffu, v, 16);
    v += __shfl_down_sync(0xffffffffu, v, 8);
    v += __shfl_down_sync(0xffffffffu, v, 4);
    v += __shfl_down_sync(0xffffffffu, v, 2);
    v += __shfl_down_sync(0xffffffffu, v, 1);
    __syncthreads();
    if ((tid & 31) == 0) red[tid >> 5] = v;
    __syncthreads();
    int s = 0;
    #pragma unroll
    for (int w = 0; w < NW; w++) s += red[w];
    return s;
}

__device__ __forceinline__ u64 rescore_key(
    int b, int c, int n,
    const float* __restrict__ x3, const float* __restrict__ x4, const float* __restrict__ x5)
{
    const float* s;
    if (n < 19200)      s = x3 + (size_t)b * 1632000 + (size_t)n * 85;
    else if (n < 24000) s = x4 + (size_t)b * 408000  + (size_t)(n - 19200) * 85;
    else                s = x5 + (size_t)b * 102000  + (size_t)(n - 24000) * 85;
    float sc = sigm(s[5 + c]) * sigm(s[4]);
    return ((u64)__float_as_uint(sc) << 32) | (unsigned)(~(unsigned)n);
}

// bitonic keep rule: new value at index i given own a, partner b.
// up = ((i & k) == 0) (descending block), lower = (i < (i^j)).
__device__ __forceinline__ u64 btn_keep(u64 a, u64 b, bool up, bool lower) {
    u64 mx = a > b ? a : b;
    u64 mn = a > b ? b : a;
    return (up == lower) ? mx : mn;
}

// ---------------- Stage 2: top-256 select + exact rescore + sort + NMS ----------------
// smem: kA u64[2048] @0 (16KB) | sS u64[512] @16384 (4KB) | hist u32[8*128] @20480 (4KB)
//       red @24576 (128B) | sInts @24704
// overlays: smask[256][8] on kA (after compact); sbox float4[256] on sS (after sort)
#define TK_SMEM 24768

__global__ __launch_bounds__(256) void topk_nms_kernel(
    const float* __restrict__ x3, const float* __restrict__ x4, const float* __restrict__ x5)
{
    extern __shared__ char sm[];
    u64* kA = (u64*)sm;
    u64* sS = (u64*)(sm + 16384);
    unsigned* hist = (unsigned*)(sm + 20480);
    int* red   = (int*)(sm + 24576);
    int* sInts = (int*)(sm + 24704);
    unsigned* smask = (unsigned*)sm;          // overlay kA
    float4* sbox = (float4*)(sm + 16384);     // overlay sS

    int bc = blockIdx.x;
    int b = bc / NC, c = bc - b * NC;
    int tid = threadIdx.x;
    const uint4* r4 = (const uint4*)(g_key16 + (size_t)bc * NPTS);

    // ---- single-pass per-warp histogram over keys with score > 0.5 ----
    for (int i = tid; i < 1024; i += 256) hist[i] = 0;
    __syncthreads();
    unsigned hbase = (tid >> 5) * 128;
    #pragma unroll 2
    for (int i = tid; i < NPTS / 8; i += 256) {
        uint4 v = __ldg(&r4[i]);
        unsigned ks[8] = { v.x & 0xffffu, v.x >> 16, v.y & 0xffffu, v.y >> 16,
                           v.z & 0xffffu, v.z >> 16, v.w & 0xffffu, v.w >> 16 };
        #pragma unroll
        for (int e = 0; e < 8; e++)
            if (ks[e] < 0x4000u) atomicAdd(&hist[hbase + (ks[e] - 0x3F80u)], 1u);
    }
    __syncthreads();
    if (tid < 128) {
        unsigned s = 0;
        #pragma unroll
        for (int w = 0; w < 8; w++) s += hist[w * 128 + tid];
        hist[tid] = s;          // per-column, no race
    }
    __syncthreads();
    if (tid == 0) {
        int cum = 0, B = -1;
        for (int q = 0; q < 128; q++) { cum += (int)hist[q]; if (cum >= KTOP) { B = q; break; } }
        sInts[1] = B;
    }
    __syncthreads();
    int B = sInts[1];

    auto countpass = [&](unsigned m) -> int {
        int cl = 0;
        for (int i = tid; i < NPTS / 8; i += 256) cl += cnt8le(__ldg(&r4[i]), m);
        return blockSum<8>(cl, red, tid);
    };

    int T0;
    if (B >= 0) {
        T0 = 0x3F80 + B;
    } else {
        // rare: fewer than 256 points with score > 0.5 -> binary search upward
        int lo = 0x3FFF, hi = 0x7FFF;
        bool found = false;
        while (!found && hi - lo > 1) {
            int m = (lo + hi) >> 1;
            int cl = countpass((unsigned)m);
            if (cl >= KTOP) { hi = m; found = (cl <= 512); }
            else lo = m;
        }
        T0 = hi;
    }

    // ---- margin collect + fused exact rescore ----
    auto collect = [&](unsigned Tm) -> int {
        __syncthreads();
        if (tid == 0) sInts[0] = 0;
        __syncthreads();
        for (int i = tid; i < NPTS / 8; i += 256) {
            uint4 v = __ldg(&r4[i]);
            int n0 = i * 8;
            unsigned ks[8] = { v.x & 0xffffu, v.x >> 16, v.y & 0xffffu, v.y >> 16,
                               v.z & 0xffffu, v.z >> 16, v.w & 0xffffu, v.w >> 16 };
            #pragma unroll
            for (int e = 0; e < 8; e++) {
                if (ks[e] <= Tm) {
                    int p = atomicAdd(&sInts[0], 1);
                    if (p < CAP) kA[p] = rescore_key(b, c, n0 + e, x3, x4, x5);
                }
            }
        }
        __syncthreads();
        return sInts[0];
    };

    unsigned Tm;
    {
        unsigned up = (unsigned)(T0 + 1) << 16;                 // bucket upper edge
        Tm = __float_as_uint(__uint_as_float(up) * 1.15f) >> 16; // covers 1.1251 approx err
        if (Tm > 0x7FFFu) Tm = 0x7FFFu;
    }
    int cnt = collect(Tm);
    if (cnt > CAP) cnt = collect((unsigned)T0);   // strict fallback
    if (cnt > CAP) cnt = CAP;

    // ---- exact trim on 32-bit score bits: max t with count >= KTOP (prefer <= 448) ----
    auto count32 = [&](unsigned t) -> int {
        int cl = 0;
        for (int i = tid; i < cnt; i += 256) cl += ((unsigned)(kA[i] >> 32) >= t);
        return blockSum<8>(cl, red, tid);
    };
    unsigned tlo = 0, thi = 0x3F800000u;
    bool tfound = false;
    while (!tfound && thi - tlo > 1) {
        unsigned m = (tlo + thi) >> 1;
        int cl = count32(m);
        if (cl >= KTOP) { tlo = m; tfound = (cl <= 448); }
        else thi = m;
    }

    // compact survivors into sS [0,512)
    __syncthreads();
    if (tid == 0) sInts[0] = 0;
    __syncthreads();
    for (int i = tid; i < cnt; i += 256) {
        u64 kk = kA[i];
        if ((unsigned)(kk >> 32) >= tlo) {
            int p = atomicAdd(&sInts[0], 1);
            if (p < 512) sS[p] = kk;
        }
    }
    __syncthreads();
    int cnt2 = min(sInts[0], 512);
    for (int i = cnt2 + tid; i < 512; i += 256) sS[i] = 0ULL;
    __syncthreads();

    // ---- hybrid register bitonic sort of 512 (desc: score desc, index asc via ~n) ----
    u64 e0 = sS[tid];
    u64 e1 = sS[tid + 256];
    __syncthreads();

    #pragma unroll
    for (unsigned k = 2; k <= 512; k <<= 1) {
        #pragma unroll
        for (unsigned j = k >> 1; j > 0; j >>= 1) {
            bool up0 = ((tid & k) == 0);
            bool up1 = (((tid + 256) & k) == 0);
            if (j == 256) {
                // partner within thread: e0 (lower) vs e1
                u64 a = e0, bb = e1;
                e0 = btn_keep(a, bb, up0, true);
                e1 = btn_keep(bb, a, up1, false);
            } else if (j >= 32) {
                sS[tid] = e0; sS[tid + 256] = e1;
                __syncthreads();
                u64 p0 = sS[tid ^ j];
                u64 p1 = sS[(tid + 256) ^ j];
                bool lower = ((tid & j) == 0);
                e0 = btn_keep(e0, p0, up0, lower);
                e1 = btn_keep(e1, p1, up1, lower);
                __syncthreads();
            } else {
                u64 p0 = __shfl_xor_sync(0xffffffffu, e0, j);
                u64 p1 = __shfl_xor_sync(0xffffffffu, e1, j);
                bool lower = ((tid & j) == 0);
                e0 = btn_keep(e0, p0, up0, lower);
                e1 = btn_keep(e1, p1, up1, lower);
            }
        }
    }
    // sorted top-256 = e0 across threads (index tid)

    // ---- NMS on exact sorted top-256 ----
    float val = __uint_as_float((unsigned)(e0 >> 32));
    unsigned n = ~(unsigned)e0;
    float4 bb4 = g_boxes4[(size_t)b * NPTS + n];
    g_cand_boxes4[(size_t)bc * KTOP + tid] = bb4;
    sbox[tid] = bb4;
    float ar = (bb4.z - bb4.x) * (bb4.w - bb4.y);
    __syncthreads();

    unsigned m8[8];
    #pragma unroll
    for (int w = 0; w < 8; w++) m8[w] = 0;
    float y0 = bb4.x, x0 = bb4.y, y1 = bb4.z, x1 = bb4.w;
    int jstart = tid & ~31;          // warp-uniform start; predicate j>tid inside
    for (int j = jstart; j < KTOP; ++j) {
        float4 bj = sbox[j];         // LDS.128 broadcast
        if (j > tid) {
            float iy = fmaxf(fminf(y1, bj.z) - fmaxf(y0, bj.x), 0.0f);
            float ix = fmaxf(fminf(x1, bj.w) - fmaxf(x0, bj.y), 0.0f);
            float inter = iy * ix;
            float arj = (bj.z - bj.x) * (bj.w - bj.y);
            float uni = ar + arj - inter;
            if (inter > NMS_T * fmaxf(uni, 1e-9f)) m8[j >> 5] |= (1u << (j & 31));
        }
    }
    #pragma unroll
    for (int w = 0; w < 8; w++) smask[tid * 8 + w] = m8[w];
    __syncthreads();

    // warp-parallel greedy suppression scan (warp 0)
    if (tid < 32) {
        unsigned kp = 0xFFFFFFFFu;         // lane w<8 owns keep word w
        for (int i = 0; i < KTOP; ++i) {
            unsigned kw = __shfl_sync(0xffffffffu, kp, i >> 5);
            bool alive = (kw >> (i & 31)) & 1u;
            if (alive && tid < 8) kp &= ~smask[i * 8 + tid];
        }
        if (tid < 8) red[tid] = (int)kp;
    }
    __syncthreads();

    bool keep = ((unsigned)red[tid >> 5] >> (tid & 31)) & 1u;
    g_kept[(size_t)bc * KTOP + tid] = keep ? val : 0.0f;
}

// ---------------- Stage 3: per-image top-100 (counting select + exact sort) ----------------
#define F_VAL  0
#define F_KEYS 81920
#define F_RED  98304
#define F_INTS 98432
#define F_SMEM 98448

__global__ __launch_bounds__(1024) void final_kernel(float* __restrict__ out)
{
    extern __shared__ char fsm[];
    uint4* v4 = (uint4*)(fsm + F_VAL);                         // 20480 floats as bits
    u64* fkeys = (u64*)(fsm + F_KEYS);
    int* red  = (int*)(fsm + F_RED);
    int* ints = (int*)(fsm + F_INTS);   // 0:cnt 1:numdet

    int b = blockIdx.x, tid = threadIdx.x;
    const uint4* row4 = (const uint4*)(g_kept + (size_t)b * NC * KTOP);

    int cpos = 0;
    for (int i = tid; i < NC * KTOP / 4; i += 1024) {
        uint4 v = row4[i];
        v4[i] = v;
        cpos += (v.x >= 1u) + (v.y >= 1u) + (v.z >= 1u) + (v.w >= 1u);
    }
    __syncthreads();
    cpos = blockSum<32>(cpos, red, tid);

    int t16 = 0;
    if (cpos >= MAXB) {
        int lo = 0, hi = 0x3F81;
        bool found = false;
        while (!found && hi - lo > 1) {
            int m = (lo + hi) >> 1;
            unsigned mb = (unsigned)m << 16;
            int cl = 0;
            for (int i = tid; i < NC * KTOP / 4; i += 1024) {
                uint4 v = v4[i];
                cl += (v.x >= mb) + (v.y >= mb) + (v.z >= mb) + (v.w >= mb);
            }
            cl = blockSum<32>(cl, red, tid);
            if (cl >= MAXB) { lo = m; found = (cl <= 256); }
            else hi = m;
        }
        t16 = lo;
    }
    unsigned Tb = (unsigned)t16 << 16;
    if (Tb < 1u) Tb = 1u;            // exclude zeros (suppressed)

    __syncthreads();
    if (tid == 0) { ints[0] = 0; ints[1] = 0; }
    __syncthreads();
    for (int i = tid; i < NC * KTOP / 4; i += 1024) {
        uint4 v = v4[i]; int n0 = i * 4; int p;
        if (v.x >= Tb) { p = atomicAdd(&ints[0], 1); if (p < FCAP) fkeys[p] = ((u64)v.x << 32) | (unsigned)(~(unsigned)n0); }
        if (v.y >= Tb) { p = atomicAdd(&ints[0], 1); if (p < FCAP) fkeys[p] = ((u64)v.y << 32) | (unsigned)(~(unsigned)(n0+1)); }
        if (v.z >= Tb) { p = atomicAdd(&ints[0], 1); if (p < FCAP) fkeys[p] = ((u64)v.z << 32) | (unsigned)(~(unsigned)(n0+2)); }
        if (v.w >= Tb) { p = atomicAdd(&ints[0], 1); if (p < FCAP) fkeys[p] = ((u64)v.w << 32) | (unsigned)(~(unsigned)(n0+3)); }
    }
    __syncthreads();
    int cnt = min(ints[0], FCAP);
    int S = 128; while (S < cnt) S <<= 1;
    for (int i = cnt + tid; i < S; i += 1024) fkeys[i] = 0ULL;
    __syncthreads();

    for (unsigned k = 2; k <= (unsigned)S; k <<= 1) {
        for (unsigned j = k >> 1; j > 0; j >>= 1) {
            for (unsigned i = tid; i < (unsigned)S; i += 1024) {
                unsigned l = i ^ j;
                if (l > i) {
                    u64 a = fkeys[i], bb = fkeys[l];
                    bool up = ((i & k) == 0);
                    if (up ? (a < bb) : (a > bb)) { fkeys[i] = bb; fkeys[l] = a; }
                }
            }
            __syncthreads();
        }
    }

    if (tid < MAXB) {
        u64 wk = fkeys[tid];
        float val = __uint_as_float((unsigned)(wk >> 32));
        bool valid = (wk != 0ULL) && (val > 0.0f);
        float4 bx = make_float4(0.f, 0.f, 0.f, 0.f);
        float cls = 0.0f, sc = 0.0f;
        if (valid) {
            unsigned flat = ~(unsigned)wk;
            int c = (int)(flat >> 8);
            int k2 = (int)(flat & 255);
            float4 bb = g_cand_boxes4[((size_t)b * NC + c) * KTOP + k2];
            bx.x = fminf(fmaxf(bb.x, 0.0f), 1.0f);
            bx.y = fminf(fmaxf(bb.y, 0.0f), 1.0f);
            bx.z = fminf(fmaxf(bb.z, 0.0f), 1.0f);
            bx.w = fminf(fmaxf(bb.w, 0.0f), 1.0f);
            cls = (float)c;
            sc = val;
            atomicAdd(&ints[1], 1);
        }
        ((float4*)out)[b * MAXB + tid] = bx;                 // nb
        out[NB * 400 + b * MAXB + tid] = cls;                // nc
        out[NB * 500 + b * MAXB + tid] = sc;                 // ns
    }
    __syncthreads();
    if (tid == 0) out[NB * 600 + b] = (float)ints[1];        // num_detections
}

// ---------------- launch ----------------
extern "C" void kernel_launch(void* const* d_in, const int* in_sizes, int n_in,
                              void* d_out, int out_size)
{
    const float* x3 = (const float*)d_in[0];
    const float* x4 = (const float*)d_in[1];
    const float* x5 = (const float*)d_in[2];
    float* out = (float*)d_out;

    cudaFuncSetAttribute(topk_nms_kernel, cudaFuncAttributeMaxDynamicSharedMemorySize, TK_SMEM);
    cudaFuncSetAttribute(final_kernel, cudaFuncAttributeMaxDynamicSharedMemorySize, F_SMEM);

    decode_kernel<<<NB * 315, 256>>>(x3, x4, x5);
    topk_nms_kernel<<<NB * NC, 256, TK_SMEM>>>(x3, x4, x5);
    final_kernel<<<NB, 1024, F_SMEM>>>(out);
}

// round 11
// speedup vs baseline: 2.3325x; 1.1972x over previous
#include <cuda_runtime.h>
#include <cstdint>
#include <math.h>

// YOLO post-process: decode -> per-class top-256 -> NMS -> per-image top-100.
#define NB 8
#define NC 80
#define NPTS 25200
#define KTOP 256
#define MAXB 100
#define NMS_T 0.6f
#define CAP 4096
#define ECAP 2048
#define FCAP 2048
#define KSEL0 0x4000u        // approx d <= 2.0 (score >= 0.5): ~2040/row, safely < CAP

typedef unsigned long long u64;

// ---------------- scratch (static device globals; no allocation) ----------------
__device__ float4 g_boxes4[NB * NPTS];                       // [B][N] yxyx
__device__ unsigned short g_key16[(size_t)NB * NC * NPTS];   // [B][C][N] approx key (smaller=better)
__device__ float4 g_cand_boxes4[NB * NC * KTOP];             // [B][C][K]
__device__ float  g_kept[NB * NC * KTOP];                    // [B][C][K]

__constant__ float c_anch[3][3][2] = {
    {{12.0f/640.0f, 16.0f/640.0f}, {19.0f/640.0f, 36.0f/640.0f}, {40.0f/640.0f, 28.0f/640.0f}},
    {{36.0f/640.0f, 75.0f/640.0f}, {76.0f/640.0f, 55.0f/640.0f}, {72.0f/640.0f, 146.0f/640.0f}},
    {{142.0f/640.0f,110.0f/640.0f},{192.0f/640.0f,243.0f/640.0f},{459.0f/640.0f,401.0f/640.0f}}};

__device__ __forceinline__ float sigm(float x) { return 1.0f / (1.0f + expf(-x)); }

// Schraudolph-style approx of e^{-x}: monotone, one-sided OVERestimate (<= +6.07% rel).
__device__ __forceinline__ float approx_em(float x) {
    float y = fmaf(x, -12102203.0f, 1065353216.0f);
    y = fminf(fmaxf(y, 0.0f), 2130706432.0f);    // clamp to [0, 0x7F000000]
    return __int_as_float((int)y);
}

// ---------------- Stage 1: decode ----------------
__global__ __launch_bounds__(256) void decode_kernel(
    const float* __restrict__ x3, const float* __restrict__ x4, const float* __restrict__ x5)
{
    __shared__ float sIn[6800];
    __shared__ float sEo1[80];          // 1 + approx e^{-obj}

    int blk = blockIdx.x;
    int b = blk / 315;
    int t = blk - b * 315;
    const float* src; int W, lvlOff, tloc, lvl;
    if (t < 240)      { lvl = 0; W = 80; lvlOff = 0;     tloc = t;       src = x3; }
    else if (t < 300) { lvl = 1; W = 40; lvlOff = 19200; tloc = t - 240; src = x4; }
    else              { lvl = 2; W = 20; lvlOff = 24000; tloc = t - 300; src = x5; }

    int tid = threadIdx.x;
    const float4* base4 = (const float4*)(src + (size_t)b * W * W * 255 + (size_t)tloc * 6800);
    for (int i = tid; i < 1700; i += 256) ((float4*)sIn)[i] = base4[i];
    __syncthreads();

    float invW = 1.0f / (float)W;
    int nGlobBase = lvlOff + tloc * 80;

    if (tid < 80) {
        const float* d = &sIn[tid * 85];
        int nLoc = tloc * 80 + tid;
        int a = nLoc % 3;
        int cell = nLoc / 3;
        int wq = cell % W;
        int hq = cell / W;
        float xc = (sigm(d[0]) + (float)wq) * invW;
        float yc = (sigm(d[1]) + (float)hq) * invW;
        float bw = expf(d[2]) * c_anch[lvl][a][0];
        float bh = expf(d[3]) * c_anch[lvl][a][1];
        float4 bx;
        bx.x = yc - bh * 0.5f;
        bx.y = xc - bw * 0.5f;
        bx.z = yc + bh * 0.5f;
        bx.w = xc + bw * 0.5f;
        g_boxes4[(size_t)b * NPTS + nGlobBase + tid] = bx;
        sEo1[tid] = 1.0f + approx_em(d[4]);
    }
    __syncthreads();

    if (tid < 160) {
        int q = tid % 20, cg = tid / 20;
        int a0 = q * 4;
        float e0 = sEo1[a0], e1 = sEo1[a0 + 1], e2 = sEo1[a0 + 2], e3 = sEo1[a0 + 3];
        const float* p = &sIn[a0 * 85 + 5 + cg];
        unsigned short* gp = g_key16 + ((size_t)b * NC + cg) * NPTS + nGlobBase + a0;
        #pragma unroll 2
        for (int j = 0; j < 10; j++) {
            // key d = (1+e^-c)(1+e^-o) = eo1 + e^-c * eo1 ; monotone inverse of score
            float d0 = fmaf(approx_em(p[0]),   e0, e0);
            float d1 = fmaf(approx_em(p[85]),  e1, e1);
            float d2 = fmaf(approx_em(p[170]), e2, e2);
            float d3 = fmaf(approx_em(p[255]), e3, e3);
            unsigned lo = __byte_perm(__float_as_uint(d0), __float_as_uint(d1), 0x7632);
            unsigned hi = __byte_perm(__float_as_uint(d2), __float_as_uint(d3), 0x7632);
            *reinterpret_cast<uint2*>(gp) = make_uint2(lo, hi);
            p += 8;
            gp += (size_t)8 * NPTS;
        }
    }
}

// ---------------- helpers ----------------
__device__ __forceinline__ int cnt8le(uint4 v, unsigned m) {
    int s = 0;
    s += ((v.x & 0xffffu) <= m); s += ((v.x >> 16) <= m);
    s += ((v.y & 0xffffu) <= m); s += ((v.y >> 16) <= m);
    s += ((v.z & 0xffffu) <= m); s += ((v.z >> 16) <= m);
    s += ((v.w & 0xffffu) <= m); s += ((v.w >> 16) <= m);
    return s;
}

template <int NW>
__device__ __forceinline__ int blockSum(int v, int* red, int tid) {
    v += __shfl_down_sync(0xffffffffu, v, 16);
    v += __shfl_down_sync(0xffffffffu, v, 8);
    v += __shfl_down_sync(0xffffffffu, v, 4);
    v += __shfl_down_sync(0xffffffffu, v, 2);
    v += __shfl_down_sync(0xffffffffu, v, 1);
    __syncthreads();
    if ((tid & 31) == 0) red[tid >> 5] = v;
    __syncthreads();
    int s = 0;
    #pragma unroll
    for (int w = 0; w < NW; w++) s += red[w];
    return s;
}

__device__ __forceinline__ u64 exact_key(
    int b, int c, int n,
    const float* __restrict__ x3, const float* __restrict__ x4, const float* __restrict__ x5)
{
    const float* s;
    if (n < 19200)      s = x3 + (size_t)b * 1632000 + (size_t)n * 85;
    else if (n < 24000) s = x4 + (size_t)b * 408000  + (size_t)(n - 19200) * 85;
    else                s = x5 + (size_t)b * 102000  + (size_t)(n - 24000) * 85;
    float sc = sigm(s[5 + c]) * sigm(s[4]);
    return ((u64)__float_as_uint(sc) << 32) | (unsigned)(~(unsigned)n);
}

// bitonic keep rule: up = ((i & k)==0); lower = element is lower index of the pair
__device__ __forceinline__ u64 btn_keep(u64 a, u64 b, bool up, bool lower) {
    u64 mx = a > b ? a : b;
    u64 mn = a > b ? b : a;
    return (up == lower) ? mx : mn;
}

__device__ __forceinline__ unsigned margin16(unsigned T0) {
    // bucket upper edge scaled by the one-sided approx-error margin (needs 1.134; use 1.15)
    unsigned Tm = __float_as_uint(__uint_as_float((T0 + 1u) << 16) * 1.15f) >> 16;
    return Tm > 0x7FFFu ? 0x7FFFu : Tm;
}

// ---------------- Stage 2: sweep-select + rescore + exact trim + sort(512) + NMS ----------------
// smem map: cnd u32[4096] @0 (16KB) | kE u64[2048] @16384 (16KB) | kX u64[512] @32768 (4KB)
//           red @36864 | sInts @36992
// overlays:  smask[256][8] @0 (on cnd) ; sbox float4[256] @16384 (on kE)
#define TK_SMEM 37056

__global__ __launch_bounds__(256) void topk_nms_kernel(
    const float* __restrict__ x3, const float* __restrict__ x4, const float* __restrict__ x5)
{
    extern __shared__ char sm[];
    unsigned* cnd  = (unsigned*)sm;
    u64* kE        = (u64*)(sm + 16384);
    u64* kX        = (u64*)(sm + 32768);
    int* red       = (int*)(sm + 36864);
    int* sInts     = (int*)(sm + 36992);
    unsigned* smask = (unsigned*)sm;           // overlay on cnd
    float4* sbox    = (float4*)(sm + 16384);   // overlay on kE (after trim)

    int bc = blockIdx.x;
    int tid = threadIdx.x;
    int b = bc / NC;
    int c = bc - b * NC;
    const uint4* r4 = (const uint4*)(g_key16 + (size_t)bc * NPTS);

    // fused single sweep: stash packed (key16<<15 | idx) for key16 <= Kthr.
    // Returns the RAW count (may exceed CAP -> caller must handle overflow!)
    auto sweep_collect = [&](unsigned Kthr) -> int {
        __syncthreads();
        if (tid == 0) sInts[0] = 0;
        __syncthreads();
        unsigned KK = Kthr | (Kthr << 16);
        for (int i = tid; i < NPTS / 8; i += 256) {
            uint4 v = __ldg(&r4[i]);
            unsigned hit = __vcmpleu2(v.x, KK) | __vcmpleu2(v.y, KK)
                         | __vcmpleu2(v.z, KK) | __vcmpleu2(v.w, KK);
            if (hit == 0u) continue;
            unsigned n0 = (unsigned)i * 8u;
            unsigned ks[8] = { v.x & 0xffffu, v.x >> 16, v.y & 0xffffu, v.y >> 16,
                               v.z & 0xffffu, v.z >> 16, v.w & 0xffffu, v.w >> 16 };
            #pragma unroll
            for (int e = 0; e < 8; e++) {
                if (ks[e] <= Kthr) {
                    int p = atomicAdd(&sInts[0], 1);
                    if (p < CAP) cnd[p] = (ks[e] << 15) | (n0 + e);
                }
            }
        }
        __syncthreads();
        return sInts[0];
    };

    // full-row count (fallback path only)
    auto global_count = [&](unsigned m) -> int {
        int cl = 0;
        for (int i = tid; i < NPTS / 8; i += 256) cl += cnt8le(__ldg(&r4[i]), m);
        return blockSum<8>(cl, red, tid);
    };

    // minimal A with count(key <= A) >= KTOP among collected
    // (== global count for A <= Kthr IF collection did not overflow)
    auto find_A = [&](int cn, unsigned Kc) -> unsigned {
        unsigned lo = 0x3F7Fu, hi = Kc;
        while (hi - lo > 1u) {
            unsigned m = (lo + hi) >> 1;
            int cl = 0;
            for (int i = tid; i < cn; i += 256) cl += ((cnd[i] >> 15) <= m);
            cl = blockSum<8>(cl, red, tid);
            if (cl >= KTOP) hi = m; else lo = m;
        }
        return hi;
    };

    unsigned Kthr = KSEL0;
    int cntRaw = sweep_collect(Kthr);
    int cnt = min(cntRaw, CAP);
    unsigned A = Kthr;

    bool need_fb = (cntRaw < KTOP) || (cntRaw > CAP);   // too few OR overflowed
    if (!need_fb) {
        A = find_A(cnt, Kthr);
        need_fb = (margin16(A) > Kthr);                 // margin band exceeds collection
    }
    if (need_fb) {
        // global minimal threshold, then re-collect at its margin (tight -> fits)
        unsigned flo = 0x3F7Fu, fhi = 0x7FFFu;
        while (fhi - flo > 1u) {
            unsigned m = (flo + fhi) >> 1;
            int cl = global_count(m);
            if (cl >= KTOP) fhi = m; else flo = m;
        }
        A = fhi;
        Kthr = margin16(fhi);
        cntRaw = sweep_collect(Kthr);
        if (cntRaw > CAP) {                             // last resort: strict collect
            Kthr = fhi;
            cntRaw = sweep_collect(fhi);
        }
        cnt = min(cntRaw, CAP);
    }
    unsigned Tsel = margin16(A);
    if (Tsel > Kthr) Tsel = Kthr;

    // exact rescore of margin survivors into kE
    auto rescore = [&](unsigned Tm) -> int {
        __syncthreads();
        if (tid == 0) sInts[0] = 0;
        __syncthreads();
        for (int i = tid; i < cnt; i += 256) {
            unsigned cd = cnd[i];
            if ((cd >> 15) <= Tm) {
                int p = atomicAdd(&sInts[0], 1);
                if (p < ECAP) kE[p] = exact_key(b, c, (int)(cd & 0x7FFFu), x3, x4, x5);
            }
        }
        __syncthreads();
        return sInts[0];
    };
    int ns = rescore(Tsel);
    if (ns > ECAP) ns = rescore(A);   // strict retry: count(<=A) is a few hundred
    if (ns > ECAP) ns = ECAP;

    // exact trim on 32-bit score bits: max t with count(score >= t) >= KTOP (prefer <= 448)
    unsigned tlo = 0, thi = 0x3F800000u;
    {
        bool done = false;
        while (!done && (thi - tlo) > 1u) {
            unsigned m = (tlo + thi) >> 1;
            int cl = 0;
            for (int i = tid; i < ns; i += 256) cl += ((unsigned)(kE[i] >> 32) >= m);
            cl = blockSum<8>(cl, red, tid);
            if (cl >= KTOP) { tlo = m; done = (cl <= 448); }
            else thi = m;
        }
    }

    // compact exact survivors into kX[512]
    __syncthreads();
    if (tid == 0) sInts[0] = 0;
    __syncthreads();
    for (int i = tid; i < ns; i += 256) {
        u64 kk = kE[i];
        if ((unsigned)(kk >> 32) >= tlo) {
            int p = atomicAdd(&sInts[0], 1);
            if (p < 512) kX[p] = kk;
        }
    }
    __syncthreads();
    int cnt2 = min(sInts[0], 512);
    for (int i = cnt2 + tid; i < 512; i += 256) kX[i] = 0ULL;
    __syncthreads();

    // hybrid register bitonic sort of 512 (desc: score desc, index asc via ~n)
    u64 e0 = kX[tid];
    u64 e1 = kX[tid + 256];
    __syncthreads();

    #pragma unroll
    for (unsigned k = 2; k <= 512; k <<= 1) {
        #pragma unroll
        for (unsigned j = k >> 1; j > 0; j >>= 1) {
            bool up0 = ((tid & k) == 0);
            bool up1 = (((tid + 256) & k) == 0);
            if (j == 256) {
                u64 a = e0, bb = e1;
                e0 = btn_keep(a, bb, up0, true);
                e1 = btn_keep(bb, a, up1, false);
            } else if (j >= 32) {
                kX[tid] = e0; kX[tid + 256] = e1;
                __syncthreads();
                u64 p0 = kX[tid ^ j];
                u64 p1 = kX[(tid + 256) ^ j];
                bool lower = ((tid & j) == 0);
                e0 = btn_keep(e0, p0, up0, lower);
                e1 = btn_keep(e1, p1, up1, lower);
                __syncthreads();
            } else {
                u64 p0 = __shfl_xor_sync(0xffffffffu, e0, j);
                u64 p1 = __shfl_xor_sync(0xffffffffu, e1, j);
                bool lower = ((tid & j) == 0);
                e0 = btn_keep(e0, p0, up0, lower);
                e1 = btn_keep(e1, p1, up1, lower);
            }
        }
    }
    // element at rank tid == e0 (cnt2 >= KTOP, so all ranks < 256 are genuine)

    // ---- NMS on the exact sorted top-256 ----
    float val = __uint_as_float((unsigned)(e0 >> 32));
    unsigned n = ~(unsigned)e0;
    float4 bb4 = g_boxes4[(size_t)b * NPTS + n];
    g_cand_boxes4[(size_t)bc * KTOP + tid] = bb4;
    sbox[tid] = bb4;
    float ar = (bb4.z - bb4.x) * (bb4.w - bb4.y);
    __syncthreads();

    unsigned m8[8];
    #pragma unroll
    for (int w = 0; w < 8; w++) m8[w] = 0;
    float y0 = bb4.x, x0 = bb4.y, y1 = bb4.z, x1 = bb4.w;
    int jstart = tid & ~31;             // warp-uniform start; predicate j>tid inside
    for (int j = jstart; j < KTOP; ++j) {
        float4 bj = sbox[j];            // broadcast LDS.128
        if (j > tid) {
            float iy = fmaxf(fminf(y1, bj.z) - fmaxf(y0, bj.x), 0.0f);
            float ix = fmaxf(fminf(x1, bj.w) - fmaxf(x0, bj.y), 0.0f);
            float inter = iy * ix;
            float arj = (bj.z - bj.x) * (bj.w - bj.y);
            float uni = ar + arj - inter;
            if (inter > NMS_T * fmaxf(uni, 1e-9f)) m8[j >> 5] |= (1u << (j & 31));
        }
    }
    #pragma unroll
    for (int w = 0; w < 8; w++) smask[tid * 8 + w] = m8[w];
    __syncthreads();

    // warp-parallel greedy suppression scan (warp 0; lane w<8 owns keep word w)
    if (tid < 32) {
        unsigned kp = 0xFFFFFFFFu;
        for (int i = 0; i < KTOP; ++i) {
            unsigned kw = __shfl_sync(0xffffffffu, kp, i >> 5);
            bool alive = (kw >> (i & 31)) & 1u;
            if (alive && tid < 8) kp &= ~smask[i * 8 + tid];
        }
        if (tid < 8) red[tid] = (int)kp;
    }
    __syncthreads();

    bool keep = ((unsigned)red[tid >> 5] >> (tid & 31)) & 1u;
    g_kept[(size_t)bc * KTOP + tid] = keep ? val : 0.0f;
}

// ---------------- Stage 3: per-image top-100 (counting select + exact sort) ----------------
#define F_VAL  0
#define F_KEYS 81920
#define F_RED  98304
#define F_INTS 98432
#define F_SMEM 98448

__global__ __launch_bounds__(1024) void final_kernel(float* __restrict__ out)
{
    extern __shared__ char fsm[];
    uint4* v4  = (uint4*)(fsm + F_VAL);
    u64* fkeys = (u64*)(fsm + F_KEYS);
    int* red   = (int*)(fsm + F_RED);
    int* ints  = (int*)(fsm + F_INTS);

    int b = blockIdx.x, tid = threadIdx.x;
    const uint4* row4 = (const uint4*)(g_kept + (size_t)b * NC * KTOP);

    int cpos = 0;
    for (int i = tid; i < NC * KTOP / 4; i += 1024) {
        uint4 v = row4[i];
        v4[i] = v;
        cpos += (v.x >= 1u) + (v.y >= 1u) + (v.z >= 1u) + (v.w >= 1u);
    }
    __syncthreads();
    cpos = blockSum<32>(cpos, red, tid);

    int t16 = 0;
    if (cpos >= MAXB) {
        int lo = 0, hi = 0x3F81;
        bool found = false;
        while (!found && hi - lo > 1) {
            int m = (lo + hi) >> 1;
            unsigned mb = (unsigned)m << 16;
            int cl = 0;
            for (int i = tid; i < NC * KTOP / 4; i += 1024) {
                uint4 v = v4[i];
                cl += (v.x >= mb) + (v.y >= mb) + (v.z >= mb) + (v.w >= mb);
            }
            cl = blockSum<32>(cl, red, tid);
            if (cl >= MAXB) { lo = m; found = (cl <= 256); }
            else hi = m;
        }
        t16 = lo;
    }
    unsigned Tb = (unsigned)t16 << 16;
    if (Tb < 1u) Tb = 1u;               // exclude suppressed zeros

    __syncthreads();
    if (tid == 0) { ints[0] = 0; ints[1] = 0; }
    __syncthreads();
    for (int i = tid; i < NC * KTOP / 4; i += 1024) {
        uint4 v = v4[i]; int n0 = i * 4; int p;
        if (v.x >= Tb) { p = atomicAdd(&ints[0], 1); if (p < FCAP) fkeys[p] = ((u64)v.x << 32) | (unsigned)(~(unsigned)n0); }
        if (v.y >= Tb) { p = atomicAdd(&ints[0], 1); if (p < FCAP) fkeys[p] = ((u64)v.y << 32) | (unsigned)(~(unsigned)(n0+1)); }
        if (v.z >= Tb) { p = atomicAdd(&ints[0], 1); if (p < FCAP) fkeys[p] = ((u64)v.z << 32) | (unsigned)(~(unsigned)(n0+2)); }
        if (v.w >= Tb) { p = atomicAdd(&ints[0], 1); if (p < FCAP) fkeys[p] = ((u64)v.w << 32) | (unsigned)(~(unsigned)(n0+3)); }
    }
    __syncthreads();
    int cnt = min(ints[0], FCAP);
    int S = 128; while (S < cnt) S <<= 1;
    for (int i = cnt + tid; i < S; i += 1024) fkeys[i] = 0ULL;
    __syncthreads();

    for (unsigned k = 2; k <= (unsigned)S; k <<= 1) {
        for (unsigned j = k >> 1; j > 0; j >>= 1) {
            for (unsigned i = tid; i < (unsigned)S; i += 1024) {
                unsigned l = i ^ j;
                if (l > i) {
                    u64 a = fkeys[i], bb = fkeys[l];
                    bool up = ((i & k) == 0);
                    if (up ? (a < bb) : (a > bb)) { fkeys[i] = bb; fkeys[l] = a; }
                }
            }
            __syncthreads();
        }
    }

    if (tid < MAXB) {
        u64 wk = fkeys[tid];
        float val = __uint_as_float((unsigned)(wk >> 32));
        bool valid = (wk != 0ULL) && (val > 0.0f);
        float4 bx = make_float4(0.f, 0.f, 0.f, 0.f);
        float cls = 0.0f, sc = 0.0f;
        if (valid) {
            unsigned flat = ~(unsigned)wk;
            int c = (int)(flat >> 8);
            int k2 = (int)(flat & 255);
            float4 bb = g_cand_boxes4[((size_t)b * NC + c) * KTOP + k2];
            bx.x = fminf(fmaxf(bb.x, 0.0f), 1.0f);
            bx.y = fminf(fmaxf(bb.y, 0.0f), 1.0f);
            bx.z = fminf(fmaxf(bb.z, 0.0f), 1.0f);
            bx.w = fminf(fmaxf(bb.w, 0.0f), 1.0f);
            cls = (float)c;
            sc = val;
            atomicAdd(&ints[1], 1);
        }
        ((float4*)out)[b * MAXB + tid] = bx;                 // nb
        out[NB * 400 + b * MAXB + tid] = cls;                // nc
        out[NB * 500 + b * MAXB + tid] = sc;                 // ns
    }
    __syncthreads();
    if (tid == 0) out[NB * 600 + b] = (float)ints[1];        // num_detections
}

// ---------------- launch ----------------
extern "C" void kernel_launch(void* const* d_in, const int* in_sizes, int n_in,
                              void* d_out, int out_size)
{
    const float* x3 = (const float*)d_in[0];
    const float* x4 = (const float*)d_in[1];
    const float* x5 = (const float*)d_in[2];
    float* out = (float*)d_out;

    cudaFuncSetAttribute(topk_nms_kernel, cudaFuncAttributeMaxDynamicSharedMemorySize, TK_SMEM);
    cudaFuncSetAttribute(final_kernel, cudaFuncAttributeMaxDynamicSharedMemorySize, F_SMEM);

    decode_kernel<<<NB * 315, 256>>>(x3, x4, x5);
    topk_nms_kernel<<<NB * NC, 256, TK_SMEM>>>(x3, x4, x5);
    final_kernel<<<NB, 1024, F_SMEM>>>(out);
}